// round 7
// baseline (speedup 1.0000x reference)
#include <cuda_runtime.h>
#include <cuda_bf16.h>
#include <math.h>

// Problem constants
#define LNUM 25
#define NN   20000
#define EE   100000
#define CC   32
#define HH   2
#define HC   64          // HH*CC
#define F1   800         // LNUM*CC
#define BNEPS 1e-5f

// GEMM1 tiling (mma.sync bf16 3-split)
#define MPAD 20096       // 157 * 128
#define NPAD 896         // 7 * 128
#define BM 128
#define BN 128
#define BK 32
#define SAP 40           // A smem pitch (elems)
#define SBP 136          // B smem pitch (elems)
#define NKITER (F1 / BK) // 25

// ---------------- scratch (device globals; no allocation allowed) -------------
__device__ float  g_xl[LNUM * NN * HC];
__device__ float  g_xr[LNUM * NN * HC];
__device__ float  g_degw[LNUM * NN * 2];     // (cnt, wsum) interleaved
__device__ float  g_denom[LNUM * NN * 2];
__device__ float  g_num[LNUM * NN * HC];
__device__ double g_bnsum[LNUM * CC];
__device__ double g_bnsq[LNUM * CC];
__device__ float  g_h[NN * F1];              // concat features pre-BN
__device__ __nv_bfloat16 g_Ah[(size_t)MPAD * F1];
__device__ __nv_bfloat16 g_Al[(size_t)MPAD * F1];
__device__ __nv_bfloat16 g_Bh[(size_t)F1 * NPAD];
__device__ __nv_bfloat16 g_Bl[(size_t)F1 * NPAD];

// ---------------- helpers -----------------------------------------------------
__device__ __forceinline__ void redAddV4(float* p, float a, float b, float c, float d) {
    asm volatile("red.global.add.v4.f32 [%0], {%1,%2,%3,%4};"
                 :: "l"(p), "f"(a), "f"(b), "f"(c), "f"(d) : "memory");
}
__device__ __forceinline__ void redAddV2(float* p, float a, float b) {
    asm volatile("red.global.add.v2.f32 [%0], {%1,%2};"
                 :: "l"(p), "f"(a), "f"(b) : "memory");
}
__device__ __forceinline__ unsigned su32(const void* p) {
    return (unsigned)__cvta_generic_to_shared(p);
}
__device__ __forceinline__ void cp16(unsigned s, const void* g) {
    asm volatile("cp.async.cg.shared.global [%0], [%1], 16;" :: "r"(s), "l"(g));
}
__device__ __forceinline__ void cp_commit() { asm volatile("cp.async.commit_group;"); }
template<int N> __device__ __forceinline__ void cp_wait() {
    asm volatile("cp.async.wait_group %0;" :: "n"(N));
}
__device__ __forceinline__ void ldsm_x4(unsigned* r, unsigned addr) {
    asm volatile("ldmatrix.sync.aligned.m8n8.x4.shared.b16 {%0,%1,%2,%3}, [%4];"
                 : "=r"(r[0]), "=r"(r[1]), "=r"(r[2]), "=r"(r[3]) : "r"(addr));
}
__device__ __forceinline__ void ldsm_x4_t(unsigned* r, unsigned addr) {
    asm volatile("ldmatrix.sync.aligned.m8n8.x4.trans.shared.b16 {%0,%1,%2,%3}, [%4];"
                 : "=r"(r[0]), "=r"(r[1]), "=r"(r[2]), "=r"(r[3]) : "r"(addr));
}
__device__ __forceinline__ void mma_bf16(float* d, const unsigned* a, const unsigned* b) {
    asm volatile("mma.sync.aligned.m16n8k16.row.col.f32.bf16.bf16.f32 "
                 "{%0,%1,%2,%3}, {%4,%5,%6,%7}, {%8,%9}, {%0,%1,%2,%3};"
                 : "+f"(d[0]), "+f"(d[1]), "+f"(d[2]), "+f"(d[3])
                 : "r"(a[0]), "r"(a[1]), "r"(a[2]), "r"(a[3]), "r"(b[0]), "r"(b[1]));
}

// ---------------- kernels ------------------------------------------------------

__global__ void k_init() {
    long i0 = (long)blockIdx.x * blockDim.x + threadIdx.x;
    long st = (long)gridDim.x * blockDim.x;
    for (long t = i0; t < (long)LNUM * NN * HC; t += st) g_num[t] = 0.f;
    for (long t = i0; t < (long)LNUM * NN * 2; t += st) { g_denom[t] = 0.f; g_degw[t] = 0.f; }
    for (long t = i0; t < (long)LNUM * CC; t += st) { g_bnsum[t] = 0.0; g_bnsq[t] = 0.0; }
}

// xl = x@Wl + bl ; xr = x@Wr + br
__global__ void k_xlxr(const float* __restrict__ x,
                       const float* __restrict__ Wl, const float* __restrict__ bl,
                       const float* __restrict__ Wr, const float* __restrict__ br) {
    long idx = (long)blockIdx.x * blockDim.x + threadIdx.x;
    if (idx >= (long)LNUM * NN * HC) return;
    int j = (int)(idx % HC);
    long r = idx / HC;
    int n = (int)(r % NN);
    int l = (int)(r / NN);
    const float* xv = x + (long)n * 5;
    float accl = bl[l * HC + j];
    float accr = br[l * HC + j];
#pragma unroll
    for (int k = 0; k < 5; k++) {
        float xk = xv[k];
        accl += xk * Wl[((long)l * 5 + k) * HC + j];
        accr += xk * Wr[((long)l * 5 + k) * HC + j];
    }
    g_xl[idx] = accl;
    g_xr[idx] = accr;
}

// in-degree + sum of incoming weights via one v2 reduction per edge
__global__ void k_deg(const int* __restrict__ ei, const float* __restrict__ ew) {
    long idx = (long)blockIdx.x * blockDim.x + threadIdx.x;
    if (idx >= (long)LNUM * EE) return;
    int e = (int)(idx % EE);
    int l = (int)(idx / EE);
    int d = __ldg(&ei[((long)l * 2 + 1) * EE + e]);
    redAddV2(&g_degw[((long)l * NN + d) * 2], 1.0f, __ldg(&ew[(long)l * EE + e]));
}

// FUSED edge pass, REAL edges only (self loops handled densely in k_node).
// One HALF-WARP per (layer, edge). All shuffles convergent.
__global__ void k_edge(const int* __restrict__ ei, const float* __restrict__ ew,
                       const float* __restrict__ We, const float* __restrict__ att) {
    long gt = (long)blockIdx.x * blockDim.x + threadIdx.x;
    long hw = gt >> 4;
    if (hw >= (long)LNUM * EE) return;
    int lane = threadIdx.x & 31;
    int sub = lane & 15;
    int e = (int)(hw % EE);
    int l = (int)(hw / EE);
    int s = __ldg(&ei[((long)l * 2 + 0) * EE + e]);
    int d = __ldg(&ei[((long)l * 2 + 1) * EE + e]);
    float w = __ldg(&ew[(long)l * EE + e]);
    int j = sub * 4;
    const float4 xl4 = *(const float4*)&g_xl[((long)l * NN + s) * HC + j];
    const float4 xr4 = *(const float4*)&g_xr[((long)l * NN + d) * HC + j];
    const float4 we4 = *(const float4*)&We[l * HC + j];
    const float4 at4 = *(const float4*)&att[l * HC + j];
    float t0 = xl4.x + xr4.x + w * we4.x;
    float t1 = xl4.y + xr4.y + w * we4.y;
    float t2 = xl4.z + xr4.z + w * we4.z;
    float t3 = xl4.w + xr4.w + w * we4.w;
    t0 = t0 > 0.f ? t0 : 0.2f * t0;
    t1 = t1 > 0.f ? t1 : 0.2f * t1;
    t2 = t2 > 0.f ? t2 : 0.2f * t2;
    t3 = t3 > 0.f ? t3 : 0.2f * t3;
    float v = t0 * at4.x + t1 * at4.y + t2 * at4.z + t3 * at4.w;
    v += __shfl_xor_sync(0xffffffffu, v, 1);
    v += __shfl_xor_sync(0xffffffffu, v, 2);
    v += __shfl_xor_sync(0xffffffffu, v, 4);
    float vother = __shfl_sync(0xffffffffu, v, (lane & 16) | 8);
    float p  = __expf(v);
    float p1 = __expf(vother);
    if (sub == 0) {
        redAddV2(&g_denom[((long)l * NN + d) * 2], p, p1);
    }
    redAddV4(&g_num[((long)l * NN + d) * HC + j],
             xl4.x * p, xl4.y * p, xl4.z * p, xl4.w * p);
}

// Node pass: dense self-loop contribution (loop attr computed inline), normalize,
// head-mean, conv bias, concat layout write, BN partial sums. grid(LNUM,10) blk(32,8)
__global__ void k_node(const float* __restrict__ conv_bias,
                       const float* __restrict__ We, const float* __restrict__ att) {
    int l = blockIdx.x;
    int c = threadIdx.x;
    int ty = threadIdx.y;
    int base = blockIdx.y * 2000;
    float cb = conv_bias[l * CC + c];
    float we0 = We[l * HC + c],       we1 = We[l * HC + 32 + c];
    float at0 = att[l * HC + c],      at1 = att[l * HC + 32 + c];
    float s1 = 0.f, s2 = 0.f;
    for (int n = base + ty; n < base + 2000; n += 8) {
        long nb = ((long)l * NN + n) * HC;
        float xl0 = g_xl[nb + c],      xl1 = g_xl[nb + 32 + c];
        float xr0 = g_xr[nb + c],      xr1 = g_xr[nb + 32 + c];
        float2 dw = *(const float2*)&g_degw[((long)l * NN + n) * 2];
        float w   = dw.y / fmaxf(dw.x, 1.0f);     // mean incoming edge weight
        float u0 = xl0 + xr0 + w * we0;
        float u1 = xl1 + xr1 + w * we1;
        u0 = u0 > 0.f ? u0 : 0.2f * u0;
        u1 = u1 > 0.f ? u1 : 0.2f * u1;
        float v0 = u0 * at0, v1 = u1 * at1;
#pragma unroll
        for (int o = 16; o; o >>= 1) {
            v0 += __shfl_xor_sync(0xffffffffu, v0, o);
            v1 += __shfl_xor_sync(0xffffffffu, v1, o);
        }
        float p0 = __expf(v0), p1 = __expf(v1);
        float2 den = *(const float2*)&g_denom[((long)l * NN + n) * 2];
        den.x += p0; den.y += p1;
        float num0 = g_num[nb + c]      + p0 * xl0;
        float num1 = g_num[nb + 32 + c] + p1 * xl1;
        float deg  = dw.x + 1.0f;
        float o_ = 0.5f * (num0 / den.x + num1 / den.y) / deg + cb;
        g_h[(long)n * F1 + l * CC + c] = o_;
        s1 += o_;
        s2 += o_ * o_;
    }
    __shared__ float sm1[8][32];
    __shared__ float sm2[8][32];
    sm1[ty][c] = s1; sm2[ty][c] = s2;
    __syncthreads();
    if (ty == 0) {
        float t1 = 0.f, t2 = 0.f;
#pragma unroll
        for (int y = 0; y < 8; y++) { t1 += sm1[y][c]; t2 += sm2[y][c]; }
        atomicAdd(&g_bnsum[l * CC + c], (double)t1);
        atomicAdd(&g_bnsq[l * CC + c], (double)t2);
    }
}

// W1 -> bf16 hi/lo with N padded to 896
__global__ void k_cvtW1(const float* __restrict__ W1) {
    long idx = (long)blockIdx.x * blockDim.x + threadIdx.x;
    if (idx >= (long)F1 * NPAD) return;
    int n = (int)(idx % NPAD);
    int k = (int)(idx / NPAD);
    float v = (n < F1) ? W1[(long)k * F1 + n] : 0.f;
    __nv_bfloat16 hi = __float2bfloat16(v);
    __nv_bfloat16 lo = __float2bfloat16(v - __bfloat162float(hi));
    g_Bh[idx] = hi;
    g_Bl[idx] = lo;
}

// seed out with b2 (gemm1 epilogue accumulates on top)
__global__ void k_outinit(const float* __restrict__ b2, float* __restrict__ out) {
    long idx = (long)blockIdx.x * blockDim.x + threadIdx.x;
    if (idx >= (long)NN * 5) return;
    out[idx] = b2[idx % 5];
}

// BN finalize + leaky(0.01) + bf16 hi/lo split into GEMM A operand (padded rows).
__global__ void k_bnfin(const float* __restrict__ gamma1, const float* __restrict__ beta1) {
    long idx = (long)blockIdx.x * blockDim.x + threadIdx.x;
    if (idx >= (long)MPAD * F1) return;
    int f = (int)(idx % F1);
    long row = idx / F1;
    float o = 0.f;
    if (row < NN) {
        double mean = g_bnsum[f] * (1.0 / NN);
        double var  = g_bnsq[f] * (1.0 / NN) - mean * mean;
        float inv = rsqrtf((float)var + BNEPS);
        o = gamma1[f] * (g_h[idx] - (float)mean) * inv + beta1[f];
        o = o > 0.f ? o : 0.01f * o;
    }
    __nv_bfloat16 hi = __float2bfloat16(o);
    __nv_bfloat16 lo = __float2bfloat16(o - __bfloat162float(hi));
    g_Ah[idx] = hi;
    g_Al[idx] = lo;
}

// GEMM1 + fused GEMM2: hid = relu(A @ W1 + b1) computed in-register, then
// out += hid_block @ W2 via lane-reduce + atomics.  bf16 3-split mma.sync.
__global__ void __launch_bounds__(256, 1)
k_gemm1(const float* __restrict__ bias, const float* __restrict__ W2,
        float* __restrict__ out) {
    extern __shared__ __nv_bfloat16 sm[];
    const int tid = threadIdx.x;
    const int wid = tid >> 5, lane = tid & 31;
    const int wm = wid >> 2, wn = wid & 3;
    const int rowBase = blockIdx.y * BM, nBase = blockIdx.x * BN;

    const int AOFF = BM * SAP;
    const int BOFF = BK * SBP;
    const int STAGE_E = 2 * AOFF + 2 * BOFF;

    float acc[4][4][4];
#pragma unroll
    for (int i = 0; i < 4; i++)
#pragma unroll
        for (int j = 0; j < 4; j++)
#pragma unroll
            for (int k = 0; k < 4; k++) acc[i][j][k] = 0.f;

    auto load_stage = [&](int ks, int buf) {
        const int k0 = ks * BK;
        __nv_bfloat16* base = sm + buf * STAGE_E;
#pragma unroll
        for (int i = 0; i < 2; i++) {
            int c = tid + i * 256;
            int row = c >> 2, seg = c & 3;
            const __nv_bfloat16* gh = g_Ah + (size_t)(rowBase + row) * F1 + k0 + seg * 8;
            const __nv_bfloat16* gl = g_Al + (size_t)(rowBase + row) * F1 + k0 + seg * 8;
            cp16(su32(base + row * SAP + seg * 8), gh);
            cp16(su32(base + AOFF + row * SAP + seg * 8), gl);
        }
#pragma unroll
        for (int i = 0; i < 2; i++) {
            int c = tid + i * 256;
            int kr = c >> 4, seg = c & 15;
            const __nv_bfloat16* gh = g_Bh + (size_t)(k0 + kr) * NPAD + nBase + seg * 8;
            const __nv_bfloat16* gl = g_Bl + (size_t)(k0 + kr) * NPAD + nBase + seg * 8;
            cp16(su32(base + 2 * AOFF + kr * SBP + seg * 8), gh);
            cp16(su32(base + 2 * AOFF + BOFF + kr * SBP + seg * 8), gl);
        }
        cp_commit();
    };

    const int grp = lane >> 3, lr = lane & 7;

    auto compute_stage = [&](int buf) {
        __nv_bfloat16* base = sm + buf * STAGE_E;
#pragma unroll
        for (int kk = 0; kk < 2; kk++) {
            unsigned afh[4][4], afl[4][4], bfh[2][4], bfl[2][4];
            int acol = kk * 16 + (grp >> 1) * 8;
#pragma unroll
            for (int mt = 0; mt < 4; mt++) {
                int arow = wm * 64 + mt * 16 + (grp & 1) * 8 + lr;
                ldsm_x4(afh[mt], su32(base + arow * SAP + acol));
                ldsm_x4(afl[mt], su32(base + AOFF + arow * SAP + acol));
            }
            int krow = kk * 16 + (grp & 1) * 8 + lr;
#pragma unroll
            for (int np = 0; np < 2; np++) {
                int ncol = wn * 32 + np * 16 + (grp >> 1) * 8;
                ldsm_x4_t(bfh[np], su32(base + 2 * AOFF + krow * SBP + ncol));
                ldsm_x4_t(bfl[np], su32(base + 2 * AOFF + BOFF + krow * SBP + ncol));
            }
#pragma unroll
            for (int mt = 0; mt < 4; mt++)
#pragma unroll
                for (int nt = 0; nt < 4; nt++) {
                    const unsigned* bh = &bfh[nt >> 1][(nt & 1) * 2];
                    const unsigned* bl = &bfl[nt >> 1][(nt & 1) * 2];
                    mma_bf16(acc[mt][nt], afh[mt], bh);
                    mma_bf16(acc[mt][nt], afh[mt], bl);
                    mma_bf16(acc[mt][nt], afl[mt], bh);
                }
        }
    };

    load_stage(0, 0);
    for (int ks = 0; ks < NKITER; ks++) {
        if (ks + 1 < NKITER) {
            load_stage(ks + 1, (ks + 1) & 1);
            cp_wait<1>();
        } else {
            cp_wait<0>();
        }
        __syncthreads();
        compute_stage(ks & 1);
        __syncthreads();
    }

    // Fused epilogue: relu(acc+bias) -> multiply by W2 -> reduce over the 4
    // lanes sharing a row -> atomicAdd into out (seeded with b2).
#pragma unroll
    for (int mt = 0; mt < 4; mt++) {
        float p2[2][5];
#pragma unroll
        for (int q = 0; q < 5; q++) { p2[0][q] = 0.f; p2[1][q] = 0.f; }
#pragma unroll
        for (int nt = 0; nt < 4; nt++) {
            int col0 = nBase + wn * 32 + nt * 8 + (lane & 3) * 2;
            float* a = acc[mt][nt];
            if (col0 < F1) {
                float b0 = bias[col0], b1 = bias[col0 + 1];
                float v0 = fmaxf(a[0] + b0, 0.f);
                float v1 = fmaxf(a[1] + b1, 0.f);
                float v2 = fmaxf(a[2] + b0, 0.f);
                float v3 = fmaxf(a[3] + b1, 0.f);
                const float* w0 = &W2[col0 * 5];
                const float* w1 = &W2[(col0 + 1) * 5];
#pragma unroll
                for (int q = 0; q < 5; q++) {
                    p2[0][q] += v0 * w0[q] + v1 * w1[q];
                    p2[1][q] += v2 * w0[q] + v3 * w1[q];
                }
            }
        }
#pragma unroll
        for (int o = 1; o <= 2; o <<= 1) {
#pragma unroll
            for (int q = 0; q < 5; q++) {
                p2[0][q] += __shfl_xor_sync(0xffffffffu, p2[0][q], o);
                p2[1][q] += __shfl_xor_sync(0xffffffffu, p2[1][q], o);
            }
        }
        int row0 = rowBase + wm * 64 + mt * 16 + (lane >> 2);
        if ((lane & 3) == 0) {
            if (row0 < NN) {
#pragma unroll
                for (int q = 0; q < 5; q++) atomicAdd(&out[row0 * 5 + q], p2[0][q]);
            }
            if (row0 + 8 < NN) {
#pragma unroll
                for (int q = 0; q < 5; q++) atomicAdd(&out[(row0 + 8) * 5 + q], p2[1][q]);
            }
        }
    }
}

// ---------------- launcher ----------------------------------------------------
extern "C" void kernel_launch(void* const* d_in, const int* in_sizes, int n_in,
                              void* d_out, int out_size) {
    const float* x     = (const float*)d_in[0];
    const int*   ei    = (const int*)d_in[1];
    const float* ew    = (const float*)d_in[2];
    const float* Wl    = (const float*)d_in[3];
    const float* bl    = (const float*)d_in[4];
    const float* Wr    = (const float*)d_in[5];
    const float* br    = (const float*)d_in[6];
    const float* We    = (const float*)d_in[7];
    const float* att   = (const float*)d_in[8];
    const float* cb    = (const float*)d_in[9];
    const float* gamma = (const float*)d_in[10];
    const float* beta  = (const float*)d_in[11];
    const float* W1    = (const float*)d_in[12];
    const float* b1    = (const float*)d_in[13];
    const float* W2    = (const float*)d_in[14];
    const float* b2    = (const float*)d_in[15];
    float* out = (float*)d_out;

    const int SMEM_BYTES = 2 * (2 * BM * SAP + 2 * BK * SBP) * (int)sizeof(__nv_bfloat16);
    cudaFuncSetAttribute(k_gemm1, cudaFuncAttributeMaxDynamicSharedMemorySize, SMEM_BYTES);

    k_init<<<4096, 256>>>();                                          // 0
    {   // xl/xr                                                        1
        long total = (long)LNUM * NN * HC;
        k_xlxr<<<(int)((total + 255) / 256), 256>>>(x, Wl, bl, Wr, br);
    }
    {   // degrees                                                      2
        long total = (long)LNUM * EE;
        k_deg<<<(int)((total + 255) / 256), 256>>>(ei, ew);
    }
    {   // fused edge pass, real edges only                             3 (ncu target)
        long threads = (long)LNUM * EE * 16;
        int blocks = (int)((threads + 255) / 256);
        k_edge<<<blocks, 256>>>(ei, ew, We, att);
    }
    {   // node pass (+ dense self loops, inline loop attr)             4
        dim3 grid(LNUM, 10);
        dim3 block(32, 8);
        k_node<<<grid, block>>>(cb, We, att);
    }
    {   // W1 split                                                     5
        long total = (long)F1 * NPAD;
        k_cvtW1<<<(int)((total + 255) / 256), 256>>>(W1);
    }
    {   // seed out with b2                                             6
        long total = (long)NN * 5;
        k_outinit<<<(int)((total + 255) / 256), 256>>>(b2, out);
    }
    {   // BN finalize + A-operand bf16 split                           7
        long total = (long)MPAD * F1;
        k_bnfin<<<(int)((total + 255) / 256), 256>>>(gamma, beta);
    }
    {   // MLP layer 1 + fused layer 2                                  8
        dim3 grid(NPAD / BN, MPAD / BM);
        k_gemm1<<<grid, 256, SMEM_BYTES>>>(b1, W2, out);
    }
    (void)in_sizes; (void)n_in; (void)out_size;
}

// round 9
// speedup vs baseline: 1.4565x; 1.4565x over previous
#include <cuda_runtime.h>
#include <cuda_bf16.h>
#include <math.h>

// Problem constants
#define LNUM 25
#define NN   20000
#define EE   100000
#define ENE  120000      // EE + NN (with self loops)
#define CC   32
#define HH   2
#define HC   64          // HH*CC
#define F1   800         // LNUM*CC
#define BNEPS 1e-5f

// GEMM1 tiling
#define MPAD 20096       // 157 * 128
#define NPAD 896         // 7 * 128
#define BM 128
#define BN 128
#define BK 32
#define SAP 40           // A smem pitch (elems)
#define SBP 136          // B smem pitch (elems)
#define NKITER (F1 / BK) // 25

// edge kernel grid
#define EGX 250                       // blocks per layer
#define NHW (EGX * 256 / 16)          // 4000 half-warps per layer
#define EITER (ENE / NHW)             // 30 (exact)

// ---------------- scratch (device globals; no allocation allowed) -------------
__device__ float  g_xl[LNUM * NN * HC];
__device__ float  g_xr[LNUM * NN * HC];
__device__ float  g_degw[LNUM * NN * 2];     // (cnt, wsum) interleaved
__device__ float  g_loop[LNUM * NN];
__device__ float  g_denom[LNUM * NN * 2];
__device__ float  g_num[LNUM * NN * HC];
__device__ double g_bnsum[LNUM * CC];
__device__ double g_bnsq[LNUM * CC];
__device__ float  g_h[NN * F1];              // concat features pre-BN
__device__ float  g_hid[NN * F1];            // MLP hidden (fp32)
__device__ __nv_bfloat16 g_Ah[(size_t)MPAD * F1];
__device__ __nv_bfloat16 g_Al[(size_t)MPAD * F1];
__device__ __nv_bfloat16 g_Bh[(size_t)F1 * NPAD];
__device__ __nv_bfloat16 g_Bl[(size_t)F1 * NPAD];

// ---------------- helpers -----------------------------------------------------
__device__ __forceinline__ void redAddV4(float* p, float a, float b, float c, float d) {
    asm volatile("red.global.add.v4.f32 [%0], {%1,%2,%3,%4};"
                 :: "l"(p), "f"(a), "f"(b), "f"(c), "f"(d) : "memory");
}
__device__ __forceinline__ void redAddV2(float* p, float a, float b) {
    asm volatile("red.global.add.v2.f32 [%0], {%1,%2};"
                 :: "l"(p), "f"(a), "f"(b) : "memory");
}
__device__ __forceinline__ unsigned su32(const void* p) {
    return (unsigned)__cvta_generic_to_shared(p);
}
__device__ __forceinline__ void cp16(unsigned s, const void* g) {
    asm volatile("cp.async.cg.shared.global [%0], [%1], 16;" :: "r"(s), "l"(g));
}
__device__ __forceinline__ void cp_commit() { asm volatile("cp.async.commit_group;"); }
template<int N> __device__ __forceinline__ void cp_wait() {
    asm volatile("cp.async.wait_group %0;" :: "n"(N));
}
__device__ __forceinline__ void ldsm_x4(unsigned* r, unsigned addr) {
    asm volatile("ldmatrix.sync.aligned.m8n8.x4.shared.b16 {%0,%1,%2,%3}, [%4];"
                 : "=r"(r[0]), "=r"(r[1]), "=r"(r[2]), "=r"(r[3]) : "r"(addr));
}
__device__ __forceinline__ void ldsm_x4_t(unsigned* r, unsigned addr) {
    asm volatile("ldmatrix.sync.aligned.m8n8.x4.trans.shared.b16 {%0,%1,%2,%3}, [%4];"
                 : "=r"(r[0]), "=r"(r[1]), "=r"(r[2]), "=r"(r[3]) : "r"(addr));
}
__device__ __forceinline__ void mma_bf16(float* d, const unsigned* a, const unsigned* b) {
    asm volatile("mma.sync.aligned.m16n8k16.row.col.f32.bf16.bf16.f32 "
                 "{%0,%1,%2,%3}, {%4,%5,%6,%7}, {%8,%9}, {%0,%1,%2,%3};"
                 : "+f"(d[0]), "+f"(d[1]), "+f"(d[2]), "+f"(d[3])
                 : "r"(a[0]), "r"(a[1]), "r"(a[2]), "r"(a[3]), "r"(b[0]), "r"(b[1]));
}

// ---------------- kernels ------------------------------------------------------

__global__ void k_init() {
    long i0 = (long)blockIdx.x * blockDim.x + threadIdx.x;
    long st = (long)gridDim.x * blockDim.x;
    for (long t = i0; t < (long)LNUM * NN * HC; t += st) g_num[t] = 0.f;
    for (long t = i0; t < (long)LNUM * NN * 2; t += st) { g_denom[t] = 0.f; g_degw[t] = 0.f; }
    for (long t = i0; t < (long)LNUM * CC; t += st) { g_bnsum[t] = 0.0; g_bnsq[t] = 0.0; }
}

// xl = x@Wl + bl ; xr = x@Wr + br
__global__ void k_xlxr(const float* __restrict__ x,
                       const float* __restrict__ Wl, const float* __restrict__ bl,
                       const float* __restrict__ Wr, const float* __restrict__ br) {
    long idx = (long)blockIdx.x * blockDim.x + threadIdx.x;
    if (idx >= (long)LNUM * NN * HC) return;
    int j = (int)(idx % HC);
    long r = idx / HC;
    int n = (int)(r % NN);
    int l = (int)(r / NN);
    const float* xv = x + (long)n * 5;
    float accl = bl[l * HC + j];
    float accr = br[l * HC + j];
#pragma unroll
    for (int k = 0; k < 5; k++) {
        float xk = xv[k];
        accl += xk * Wl[((long)l * 5 + k) * HC + j];
        accr += xk * Wr[((long)l * 5 + k) * HC + j];
    }
    g_xl[idx] = accl;
    g_xr[idx] = accr;
}

// in-degree + sum of incoming weights via one v2 reduction per edge
__global__ void k_deg(const int* __restrict__ ei, const float* __restrict__ ew) {
    long idx = (long)blockIdx.x * blockDim.x + threadIdx.x;
    if (idx >= (long)LNUM * EE) return;
    int e = (int)(idx % EE);
    int l = (int)(idx / EE);
    int d = __ldg(&ei[((long)l * 2 + 1) * EE + e]);
    redAddV2(&g_degw[((long)l * NN + d) * 2], 1.0f, __ldg(&ew[(long)l * EE + e]));
}

__global__ void k_loopfin() {
    long idx = (long)blockIdx.x * blockDim.x + threadIdx.x;
    if (idx >= (long)LNUM * NN) return;
    float cnt = g_degw[idx * 2 + 0];
    float ws  = g_degw[idx * 2 + 1];
    g_loop[idx] = ws / fmaxf(cnt, 1.0f);
}

// FUSED edge pass.  2D grid: blockIdx.y = layer.  Each half-warp handles
// EITER=30 edges with stride NHW (exact division => fully uniform control flow,
// all shuffles convergent; iterations 25-29 are uniformly self loops).
// We/att hoisted out of the loop (loop-invariant per lane).
__global__ void __launch_bounds__(256) k_edge(const int* __restrict__ ei,
                                              const float* __restrict__ ew,
                                              const float* __restrict__ We,
                                              const float* __restrict__ att) {
    const int l = blockIdx.y;
    const int lane = threadIdx.x & 31;
    const int sub = lane & 15;
    const int j = sub * 4;
    const int hw0 = (blockIdx.x * 256 + threadIdx.x) >> 4;

    const float4 we4 = *(const float4*)&We[l * HC + j];
    const float4 at4 = *(const float4*)&att[l * HC + j];
    const int*   srcp = ei + (long)l * 2 * EE;
    const int*   dstp = srcp + EE;
    const float* ewp  = ew + (long)l * EE;
    const float* xlL  = g_xl + (long)l * NN * HC;
    const float* xrL  = g_xr + (long)l * NN * HC;
    const float* loopL = g_loop + (long)l * NN;
    float* denomL = g_denom + (long)l * NN * 2;
    float* numL   = g_num + (long)l * NN * HC;

#pragma unroll 2
    for (int it = 0; it < EITER; it++) {
        int e = hw0 + it * NHW;
        int s, d; float w;
        if (e < EE) {
            s = __ldg(srcp + e);
            d = __ldg(dstp + e);
            w = __ldg(ewp + e);
        } else {
            s = e - EE; d = s;
            w = __ldg(loopL + s);
        }
        const float4 xl4 = *(const float4*)&xlL[(long)s * HC + j];
        const float4 xr4 = *(const float4*)&xrL[(long)d * HC + j];
        float t0 = xl4.x + xr4.x + w * we4.x;
        float t1 = xl4.y + xr4.y + w * we4.y;
        float t2 = xl4.z + xr4.z + w * we4.z;
        float t3 = xl4.w + xr4.w + w * we4.w;
        t0 = t0 > 0.f ? t0 : 0.2f * t0;
        t1 = t1 > 0.f ? t1 : 0.2f * t1;
        t2 = t2 > 0.f ? t2 : 0.2f * t2;
        t3 = t3 > 0.f ? t3 : 0.2f * t3;
        float v = t0 * at4.x + t1 * at4.y + t2 * at4.z + t3 * at4.w;
        v += __shfl_xor_sync(0xffffffffu, v, 1);
        v += __shfl_xor_sync(0xffffffffu, v, 2);
        v += __shfl_xor_sync(0xffffffffu, v, 4);
        float vother = __shfl_sync(0xffffffffu, v, (lane & 16) | 8);
        float p  = __expf(v);
        float p1 = __expf(vother);
        if (sub == 0) {
            redAddV2(&denomL[d * 2], p, p1);
        }
        redAddV4(&numL[(long)d * HC + j],
                 xl4.x * p, xl4.y * p, xl4.z * p, xl4.w * p);
    }
}

// Node pass: normalize, head-mean, conv bias, concat layout write, BN partials.
__global__ void k_node(const float* __restrict__ conv_bias) {
    int l = blockIdx.x;
    int c = threadIdx.x;
    int ty = threadIdx.y;
    int base = blockIdx.y * 2000;
    float cb = conv_bias[l * CC + c];
    float s1 = 0.f, s2 = 0.f;
    for (int n = base + ty; n < base + 2000; n += 8) {
        float2 den = *(const float2*)&g_denom[((long)l * NN + n) * 2];
        float deg  = g_degw[((long)l * NN + n) * 2] + 1.0f;
        long nb = ((long)l * NN + n) * HC;
        float o = 0.5f * (g_num[nb + c] / den.x + g_num[nb + 32 + c] / den.y) / deg + cb;
        g_h[(long)n * F1 + l * CC + c] = o;
        s1 += o;
        s2 += o * o;
    }
    __shared__ float sm1[8][32];
    __shared__ float sm2[8][32];
    sm1[ty][c] = s1; sm2[ty][c] = s2;
    __syncthreads();
    if (ty == 0) {
        float t1 = 0.f, t2 = 0.f;
#pragma unroll
        for (int y = 0; y < 8; y++) { t1 += sm1[y][c]; t2 += sm2[y][c]; }
        atomicAdd(&g_bnsum[l * CC + c], (double)t1);
        atomicAdd(&g_bnsq[l * CC + c], (double)t2);
    }
}

// BN finalize + leaky(0.01) + bf16 hi/lo split into GEMM A operand (padded rows).
__global__ void k_bnfin(const float* __restrict__ gamma1, const float* __restrict__ beta1) {
    long idx = (long)blockIdx.x * blockDim.x + threadIdx.x;
    if (idx >= (long)MPAD * F1) return;
    int f = (int)(idx % F1);
    long row = idx / F1;
    float o = 0.f;
    if (row < NN) {
        double mean = g_bnsum[f] * (1.0 / NN);
        double var  = g_bnsq[f] * (1.0 / NN) - mean * mean;
        float inv = rsqrtf((float)var + BNEPS);
        o = gamma1[f] * (g_h[idx] - (float)mean) * inv + beta1[f];
        o = o > 0.f ? o : 0.01f * o;
    }
    __nv_bfloat16 hi = __float2bfloat16(o);
    __nv_bfloat16 lo = __float2bfloat16(o - __bfloat162float(hi));
    g_Ah[idx] = hi;
    g_Al[idx] = lo;
}

// W1 -> bf16 hi/lo with N padded to 896
__global__ void k_cvtW1(const float* __restrict__ W1) {
    long idx = (long)blockIdx.x * blockDim.x + threadIdx.x;
    if (idx >= (long)F1 * NPAD) return;
    int n = (int)(idx % NPAD);
    int k = (int)(idx / NPAD);
    float v = (n < F1) ? W1[(long)k * F1 + n] : 0.f;
    __nv_bfloat16 hi = __float2bfloat16(v);
    __nv_bfloat16 lo = __float2bfloat16(v - __bfloat162float(hi));
    g_Bh[idx] = hi;
    g_Bl[idx] = lo;
}

// GEMM1: g_hid = relu(A[20000,800] @ W1[800,800] + b1), bf16 3-split tensor MMA.
__global__ void __launch_bounds__(256, 1) k_gemm1(const float* __restrict__ bias) {
    extern __shared__ __nv_bfloat16 sm[];
    const int tid = threadIdx.x;
    const int wid = tid >> 5, lane = tid & 31;
    const int wm = wid >> 2, wn = wid & 3;
    const int rowBase = blockIdx.y * BM, nBase = blockIdx.x * BN;

    const int AOFF = BM * SAP;
    const int BOFF = BK * SBP;
    const int STAGE_E = 2 * AOFF + 2 * BOFF;

    float acc[4][4][4];
#pragma unroll
    for (int i = 0; i < 4; i++)
#pragma unroll
        for (int j = 0; j < 4; j++)
#pragma unroll
            for (int k = 0; k < 4; k++) acc[i][j][k] = 0.f;

    auto load_stage = [&](int ks, int buf) {
        const int k0 = ks * BK;
        __nv_bfloat16* base = sm + buf * STAGE_E;
#pragma unroll
        for (int i = 0; i < 2; i++) {
            int c = tid + i * 256;
            int row = c >> 2, seg = c & 3;
            const __nv_bfloat16* gh = g_Ah + (size_t)(rowBase + row) * F1 + k0 + seg * 8;
            const __nv_bfloat16* gl = g_Al + (size_t)(rowBase + row) * F1 + k0 + seg * 8;
            cp16(su32(base + row * SAP + seg * 8), gh);
            cp16(su32(base + AOFF + row * SAP + seg * 8), gl);
        }
#pragma unroll
        for (int i = 0; i < 2; i++) {
            int c = tid + i * 256;
            int kr = c >> 4, seg = c & 15;
            const __nv_bfloat16* gh = g_Bh + (size_t)(k0 + kr) * NPAD + nBase + seg * 8;
            const __nv_bfloat16* gl = g_Bl + (size_t)(k0 + kr) * NPAD + nBase + seg * 8;
            cp16(su32(base + 2 * AOFF + kr * SBP + seg * 8), gh);
            cp16(su32(base + 2 * AOFF + BOFF + kr * SBP + seg * 8), gl);
        }
        cp_commit();
    };

    const int grp = lane >> 3, lr = lane & 7;

    auto compute_stage = [&](int buf) {
        __nv_bfloat16* base = sm + buf * STAGE_E;
#pragma unroll
        for (int kk = 0; kk < 2; kk++) {
            unsigned afh[4][4], afl[4][4], bfh[2][4], bfl[2][4];
            int acol = kk * 16 + (grp >> 1) * 8;
#pragma unroll
            for (int mt = 0; mt < 4; mt++) {
                int arow = wm * 64 + mt * 16 + (grp & 1) * 8 + lr;
                ldsm_x4(afh[mt], su32(base + arow * SAP + acol));
                ldsm_x4(afl[mt], su32(base + AOFF + arow * SAP + acol));
            }
            int krow = kk * 16 + (grp & 1) * 8 + lr;
#pragma unroll
            for (int np = 0; np < 2; np++) {
                int ncol = wn * 32 + np * 16 + (grp >> 1) * 8;
                ldsm_x4_t(bfh[np], su32(base + 2 * AOFF + krow * SBP + ncol));
                ldsm_x4_t(bfl[np], su32(base + 2 * AOFF + BOFF + krow * SBP + ncol));
            }
#pragma unroll
            for (int mt = 0; mt < 4; mt++)
#pragma unroll
                for (int nt = 0; nt < 4; nt++) {
                    const unsigned* bh = &bfh[nt >> 1][(nt & 1) * 2];
                    const unsigned* bl = &bfl[nt >> 1][(nt & 1) * 2];
                    mma_bf16(acc[mt][nt], afh[mt], bh);
                    mma_bf16(acc[mt][nt], afh[mt], bl);
                    mma_bf16(acc[mt][nt], afl[mt], bh);
                }
        }
    };

    load_stage(0, 0);
    for (int ks = 0; ks < NKITER; ks++) {
        if (ks + 1 < NKITER) {
            load_stage(ks + 1, (ks + 1) & 1);
            cp_wait<1>();
        } else {
            cp_wait<0>();
        }
        __syncthreads();
        compute_stage(ks & 1);
        __syncthreads();
    }

#pragma unroll
    for (int mt = 0; mt < 4; mt++) {
#pragma unroll
        for (int nt = 0; nt < 4; nt++) {
            int row0 = rowBase + wm * 64 + mt * 16 + (lane >> 2);
            int col0 = nBase + wn * 32 + nt * 8 + (lane & 3) * 2;
            float* a = acc[mt][nt];
            if (col0 < F1) {
                float bsum0 = bias[col0];
                float bsum1 = (col0 + 1 < F1) ? bias[col0 + 1] : 0.f;
                if (row0 < NN) {
                    float v0 = a[0] + bsum0;
                    g_hid[(long)row0 * F1 + col0] = v0 > 0.f ? v0 : 0.f;
                    if (col0 + 1 < F1) {
                        float v1 = a[1] + bsum1;
                        g_hid[(long)row0 * F1 + col0 + 1] = v1 > 0.f ? v1 : 0.f;
                    }
                }
                if (row0 + 8 < NN) {
                    float v2 = a[2] + bsum0;
                    g_hid[(long)(row0 + 8) * F1 + col0] = v2 > 0.f ? v2 : 0.f;
                    if (col0 + 1 < F1) {
                        float v3 = a[3] + bsum1;
                        g_hid[(long)(row0 + 8) * F1 + col0 + 1] = v3 > 0.f ? v3 : 0.f;
                    }
                }
            }
        }
    }
}

// out = g_hid[20000,800] @ W2[800,5] + b2. One warp per row.
__global__ void k_gemm2(const float* __restrict__ W2, const float* __restrict__ b2,
                        float* __restrict__ out) {
    long w = ((long)blockIdx.x * blockDim.x + threadIdx.x) >> 5;
    int lane = threadIdx.x & 31;
    if (w >= NN) return;
    const float* hr = g_hid + w * F1;
    float a0 = 0.f, a1 = 0.f, a2 = 0.f, a3 = 0.f, a4 = 0.f;
    for (int k4 = lane * 4; k4 < F1; k4 += 128) {
        float4 hv = *(const float4*)(hr + k4);
        float hs[4] = {hv.x, hv.y, hv.z, hv.w};
#pragma unroll
        for (int t = 0; t < 4; t++) {
            const float* wv = W2 + (k4 + t) * 5;
            float hk = hs[t];
            a0 += hk * wv[0];
            a1 += hk * wv[1];
            a2 += hk * wv[2];
            a3 += hk * wv[3];
            a4 += hk * wv[4];
        }
    }
#pragma unroll
    for (int o = 16; o; o >>= 1) {
        a0 += __shfl_xor_sync(0xffffffffu, a0, o);
        a1 += __shfl_xor_sync(0xffffffffu, a1, o);
        a2 += __shfl_xor_sync(0xffffffffu, a2, o);
        a3 += __shfl_xor_sync(0xffffffffu, a3, o);
        a4 += __shfl_xor_sync(0xffffffffu, a4, o);
    }
    if (lane == 0) {
        out[w * 5 + 0] = a0 + b2[0];
        out[w * 5 + 1] = a1 + b2[1];
        out[w * 5 + 2] = a2 + b2[2];
        out[w * 5 + 3] = a3 + b2[3];
        out[w * 5 + 4] = a4 + b2[4];
    }
}

// ---------------- launcher ----------------------------------------------------
extern "C" void kernel_launch(void* const* d_in, const int* in_sizes, int n_in,
                              void* d_out, int out_size) {
    const float* x     = (const float*)d_in[0];
    const int*   ei    = (const int*)d_in[1];
    const float* ew    = (const float*)d_in[2];
    const float* Wl    = (const float*)d_in[3];
    const float* bl    = (const float*)d_in[4];
    const float* Wr    = (const float*)d_in[5];
    const float* br    = (const float*)d_in[6];
    const float* We    = (const float*)d_in[7];
    const float* att   = (const float*)d_in[8];
    const float* cb    = (const float*)d_in[9];
    const float* gamma = (const float*)d_in[10];
    const float* beta  = (const float*)d_in[11];
    const float* W1    = (const float*)d_in[12];
    const float* b1    = (const float*)d_in[13];
    const float* W2    = (const float*)d_in[14];
    const float* b2    = (const float*)d_in[15];
    float* out = (float*)d_out;

    const int SMEM_BYTES = 2 * (2 * BM * SAP + 2 * BK * SBP) * (int)sizeof(__nv_bfloat16);
    cudaFuncSetAttribute(k_gemm1, cudaFuncAttributeMaxDynamicSharedMemorySize, SMEM_BYTES);

    k_init<<<4096, 256>>>();                                          // 0
    {   // xl/xr                                                        1
        long total = (long)LNUM * NN * HC;
        k_xlxr<<<(int)((total + 255) / 256), 256>>>(x, Wl, bl, Wr, br);
    }
    {   // degrees                                                      2
        long total = (long)LNUM * EE;
        k_deg<<<(int)((total + 255) / 256), 256>>>(ei, ew);
    }
    {   // loop attr                                                    3
        long total = (long)LNUM * NN;
        k_loopfin<<<(int)((total + 255) / 256), 256>>>();
    }
    {   // W1 split                                                     4
        long total = (long)F1 * NPAD;
        k_cvtW1<<<(int)((total + 255) / 256), 256>>>(W1);
    }
    {   // fused edge pass: layer per blockIdx.y, uniform 30 edges/half-warp  5 (ncu)
        dim3 grid(EGX, LNUM);
        k_edge<<<grid, 256>>>(ei, ew, We, att);
    }
    {   // node pass                                                    6
        dim3 grid(LNUM, 10);
        dim3 block(32, 8);
        k_node<<<grid, block>>>(cb);
    }
    {   // BN finalize + A-operand bf16 split                           7
        long total = (long)MPAD * F1;
        k_bnfin<<<(int)((total + 255) / 256), 256>>>(gamma, beta);
    }
    {   // MLP layer 1 (tensor cores)                                   8
        dim3 grid(NPAD / BN, MPAD / BM);
        k_gemm1<<<grid, 256, SMEM_BYTES>>>(b1);
    }
    {   // MLP layer 2                                                  9
        long threads = (long)NN * 32;
        k_gemm2<<<(int)((threads + 255) / 256), 256>>>(W2, b2, out);
    }
    (void)in_sizes; (void)n_in; (void)out_size;
}

// round 11
// speedup vs baseline: 1.5135x; 1.0391x over previous
#include <cuda_runtime.h>
#include <cuda_bf16.h>
#include <math.h>

// Problem constants
#define LNUM 25
#define NN   20000
#define EE   100000
#define ENE  120000      // EE + NN (with self loops)
#define CC   32
#define HH   2
#define HC   64          // HH*CC
#define F1   800         // LNUM*CC
#define BNEPS 1e-5f

// GEMM1 tiling: 128x64 blocks, bf16 3-split mma.sync
#define MPAD 20096       // 157 * 128
#define NPAD 832         // 13 * 64
#define BM 128
#define BN 64
#define BK 32
#define SAP 40           // A smem pitch (elems): 80B rows, conflict-free ldmatrix
#define SBP 72           // B smem pitch (elems): 144B rows, conflict-free ldmatrix
#define NKITER (F1 / BK) // 25

// edge kernel grid
#define EGX 250                       // blocks per layer
#define NHW (EGX * 256 / 16)          // 4000 half-warps per layer
#define EITER (ENE / NHW)             // 30 (exact)

// ---------------- scratch (device globals; no allocation allowed) -------------
__device__ float  g_xl[LNUM * NN * HC];
__device__ float  g_xr[LNUM * NN * HC];
__device__ float  g_degw[LNUM * NN * 2];     // (cnt, wsum) interleaved
__device__ float  g_denom[LNUM * NN * 2];
__device__ float  g_num[LNUM * NN * HC];
__device__ double g_bnsum[LNUM * CC];
__device__ double g_bnsq[LNUM * CC];
__device__ float  g_h[NN * F1];              // concat features pre-BN
__device__ float  g_hid[NN * F1];            // MLP hidden (fp32)
__device__ __nv_bfloat16 g_Ah[(size_t)MPAD * F1];
__device__ __nv_bfloat16 g_Al[(size_t)MPAD * F1];
__device__ __nv_bfloat16 g_Bh[(size_t)F1 * NPAD];
__device__ __nv_bfloat16 g_Bl[(size_t)F1 * NPAD];

// ---------------- helpers -----------------------------------------------------
__device__ __forceinline__ void redAddV4(float* p, float a, float b, float c, float d) {
    asm volatile("red.global.add.v4.f32 [%0], {%1,%2,%3,%4};"
                 :: "l"(p), "f"(a), "f"(b), "f"(c), "f"(d) : "memory");
}
__device__ __forceinline__ void redAddV2(float* p, float a, float b) {
    asm volatile("red.global.add.v2.f32 [%0], {%1,%2};"
                 :: "l"(p), "f"(a), "f"(b) : "memory");
}
__device__ __forceinline__ unsigned su32(const void* p) {
    return (unsigned)__cvta_generic_to_shared(p);
}
__device__ __forceinline__ void cp16(unsigned s, const void* g) {
    asm volatile("cp.async.cg.shared.global [%0], [%1], 16;" :: "r"(s), "l"(g));
}
__device__ __forceinline__ void cp_commit() { asm volatile("cp.async.commit_group;"); }
template<int N> __device__ __forceinline__ void cp_wait() {
    asm volatile("cp.async.wait_group %0;" :: "n"(N));
}
__device__ __forceinline__ void ldsm_x4(unsigned* r, unsigned addr) {
    asm volatile("ldmatrix.sync.aligned.m8n8.x4.shared.b16 {%0,%1,%2,%3}, [%4];"
                 : "=r"(r[0]), "=r"(r[1]), "=r"(r[2]), "=r"(r[3]) : "r"(addr));
}
__device__ __forceinline__ void ldsm_x4_t(unsigned* r, unsigned addr) {
    asm volatile("ldmatrix.sync.aligned.m8n8.x4.trans.shared.b16 {%0,%1,%2,%3}, [%4];"
                 : "=r"(r[0]), "=r"(r[1]), "=r"(r[2]), "=r"(r[3]) : "r"(addr));
}
__device__ __forceinline__ void mma_bf16(float* d, const unsigned* a, const unsigned* b) {
    asm volatile("mma.sync.aligned.m16n8k16.row.col.f32.bf16.bf16.f32 "
                 "{%0,%1,%2,%3}, {%4,%5,%6,%7}, {%8,%9}, {%0,%1,%2,%3};"
                 : "+f"(d[0]), "+f"(d[1]), "+f"(d[2]), "+f"(d[3])
                 : "r"(a[0]), "r"(a[1]), "r"(a[2]), "r"(a[3]), "r"(b[0]), "r"(b[1]));
}

// ---------------- kernels ------------------------------------------------------

__global__ void k_init() {
    long i0 = (long)blockIdx.x * blockDim.x + threadIdx.x;
    long st = (long)gridDim.x * blockDim.x;
    for (long t = i0; t < (long)LNUM * NN * HC; t += st) g_num[t] = 0.f;
    for (long t = i0; t < (long)LNUM * NN * 2; t += st) { g_denom[t] = 0.f; g_degw[t] = 0.f; }
    for (long t = i0; t < (long)LNUM * CC; t += st) { g_bnsum[t] = 0.0; g_bnsq[t] = 0.0; }
}

// xl = x@Wl + bl ; xr = x@Wr + br
__global__ void k_xlxr(const float* __restrict__ x,
                       const float* __restrict__ Wl, const float* __restrict__ bl,
                       const float* __restrict__ Wr, const float* __restrict__ br) {
    long idx = (long)blockIdx.x * blockDim.x + threadIdx.x;
    if (idx >= (long)LNUM * NN * HC) return;
    int j = (int)(idx % HC);
    long r = idx / HC;
    int n = (int)(r % NN);
    int l = (int)(r / NN);
    const float* xv = x + (long)n * 5;
    float accl = bl[l * HC + j];
    float accr = br[l * HC + j];
#pragma unroll
    for (int k = 0; k < 5; k++) {
        float xk = xv[k];
        accl += xk * Wl[((long)l * 5 + k) * HC + j];
        accr += xk * Wr[((long)l * 5 + k) * HC + j];
    }
    g_xl[idx] = accl;
    g_xr[idx] = accr;
}

// in-degree + sum of incoming weights via one v2 reduction per edge
__global__ void k_deg(const int* __restrict__ ei, const float* __restrict__ ew) {
    long idx = (long)blockIdx.x * blockDim.x + threadIdx.x;
    if (idx >= (long)LNUM * EE) return;
    int e = (int)(idx % EE);
    int l = (int)(idx / EE);
    int d = __ldg(&ei[((long)l * 2 + 1) * EE + e]);
    redAddV2(&g_degw[((long)l * NN + d) * 2], 1.0f, __ldg(&ew[(long)l * EE + e]));
}

// FUSED edge pass.  2D grid: blockIdx.y = layer.  Each half-warp handles
// EITER=30 edges with stride NHW (exact => fully uniform control flow; iters
// 25-29 are uniformly self loops, whose attr = wsum/max(cnt,1) from g_degw).
__global__ void __launch_bounds__(256) k_edge(const int* __restrict__ ei,
                                              const float* __restrict__ ew,
                                              const float* __restrict__ We,
                                              const float* __restrict__ att) {
    const int l = blockIdx.y;
    const int lane = threadIdx.x & 31;
    const int sub = lane & 15;
    const int j = sub * 4;
    const int hw0 = (blockIdx.x * 256 + threadIdx.x) >> 4;

    const float4 we4 = *(const float4*)&We[l * HC + j];
    const float4 at4 = *(const float4*)&att[l * HC + j];
    const int*   srcp = ei + (long)l * 2 * EE;
    const int*   dstp = srcp + EE;
    const float* ewp  = ew + (long)l * EE;
    const float* xlL  = g_xl + (long)l * NN * HC;
    const float* xrL  = g_xr + (long)l * NN * HC;
    const float* degwL = g_degw + (long)l * NN * 2;
    float* denomL = g_denom + (long)l * NN * 2;
    float* numL   = g_num + (long)l * NN * HC;

#pragma unroll 2
    for (int it = 0; it < EITER; it++) {
        int e = hw0 + it * NHW;
        int s, d; float w;
        if (e < EE) {
            s = __ldg(srcp + e);
            d = __ldg(dstp + e);
            w = __ldg(ewp + e);
        } else {
            s = e - EE; d = s;
            float2 dw = *(const float2*)&degwL[(long)s * 2];
            w = dw.y / fmaxf(dw.x, 1.0f);
        }
        const float4 xl4 = *(const float4*)&xlL[(long)s * HC + j];
        const float4 xr4 = *(const float4*)&xrL[(long)d * HC + j];
        float t0 = xl4.x + xr4.x + w * we4.x;
        float t1 = xl4.y + xr4.y + w * we4.y;
        float t2 = xl4.z + xr4.z + w * we4.z;
        float t3 = xl4.w + xr4.w + w * we4.w;
        t0 = t0 > 0.f ? t0 : 0.2f * t0;
        t1 = t1 > 0.f ? t1 : 0.2f * t1;
        t2 = t2 > 0.f ? t2 : 0.2f * t2;
        t3 = t3 > 0.f ? t3 : 0.2f * t3;
        float v = t0 * at4.x + t1 * at4.y + t2 * at4.z + t3 * at4.w;
        v += __shfl_xor_sync(0xffffffffu, v, 1);
        v += __shfl_xor_sync(0xffffffffu, v, 2);
        v += __shfl_xor_sync(0xffffffffu, v, 4);
        float vother = __shfl_sync(0xffffffffu, v, (lane & 16) | 8);
        float p  = __expf(v);
        float p1 = __expf(vother);
        if (sub == 0) {
            redAddV2(&denomL[(long)d * 2], p, p1);
        }
        redAddV4(&numL[(long)d * HC + j],
                 xl4.x * p, xl4.y * p, xl4.z * p, xl4.w * p);
    }
}

// Node pass: normalize, head-mean, conv bias, concat layout write, BN partials.
__global__ void k_node(const float* __restrict__ conv_bias) {
    int l = blockIdx.x;
    int c = threadIdx.x;
    int ty = threadIdx.y;
    int base = blockIdx.y * 2000;
    float cb = conv_bias[l * CC + c];
    float s1 = 0.f, s2 = 0.f;
    for (int n = base + ty; n < base + 2000; n += 8) {
        float2 den = *(const float2*)&g_denom[((long)l * NN + n) * 2];
        float deg  = g_degw[((long)l * NN + n) * 2] + 1.0f;
        long nb = ((long)l * NN + n) * HC;
        float o = 0.5f * (g_num[nb + c] / den.x + g_num[nb + 32 + c] / den.y) / deg + cb;
        g_h[(long)n * F1 + l * CC + c] = o;
        s1 += o;
        s2 += o * o;
    }
    __shared__ float sm1[8][32];
    __shared__ float sm2[8][32];
    sm1[ty][c] = s1; sm2[ty][c] = s2;
    __syncthreads();
    if (ty == 0) {
        float t1 = 0.f, t2 = 0.f;
#pragma unroll
        for (int y = 0; y < 8; y++) { t1 += sm1[y][c]; t2 += sm2[y][c]; }
        atomicAdd(&g_bnsum[l * CC + c], (double)t1);
        atomicAdd(&g_bnsq[l * CC + c], (double)t2);
    }
}

// BN finalize + leaky(0.01) + bf16 hi/lo split into GEMM A operand (padded rows).
__global__ void k_bnfin(const float* __restrict__ gamma1, const float* __restrict__ beta1) {
    long idx = (long)blockIdx.x * blockDim.x + threadIdx.x;
    if (idx >= (long)MPAD * F1) return;
    int f = (int)(idx % F1);
    long row = idx / F1;
    float o = 0.f;
    if (row < NN) {
        double mean = g_bnsum[f] * (1.0 / NN);
        double var  = g_bnsq[f] * (1.0 / NN) - mean * mean;
        float inv = rsqrtf((float)var + BNEPS);
        o = gamma1[f] * (g_h[idx] - (float)mean) * inv + beta1[f];
        o = o > 0.f ? o : 0.01f * o;
    }
    __nv_bfloat16 hi = __float2bfloat16(o);
    __nv_bfloat16 lo = __float2bfloat16(o - __bfloat162float(hi));
    g_Ah[idx] = hi;
    g_Al[idx] = lo;
}

// W1 -> bf16 hi/lo with N padded to 832
__global__ void k_cvtW1(const float* __restrict__ W1) {
    long idx = (long)blockIdx.x * blockDim.x + threadIdx.x;
    if (idx >= (long)F1 * NPAD) return;
    int n = (int)(idx % NPAD);
    int k = (int)(idx / NPAD);
    float v = (n < F1) ? W1[(long)k * F1 + n] : 0.f;
    __nv_bfloat16 hi = __float2bfloat16(v);
    __nv_bfloat16 lo = __float2bfloat16(v - __bfloat162float(hi));
    g_Bh[idx] = hi;
    g_Bl[idx] = lo;
}

// GEMM1: g_hid = relu(A[20000,800] @ W1[800,800] + b1), bf16 3-split mma.sync.
// 128x64 block tile, 8 warps of 32x32, 2 blocks/SM target.
__global__ void __launch_bounds__(256, 2) k_gemm1(const float* __restrict__ bias) {
    extern __shared__ __nv_bfloat16 sm[];
    const int tid = threadIdx.x;
    const int wid = tid >> 5, lane = tid & 31;
    const int wm = wid >> 1, wn = wid & 1;      // 4 x 2 warp grid, 32x32 per warp
    const int rowBase = blockIdx.y * BM, nBase = blockIdx.x * BN;

    const int AOFF = BM * SAP;                  // 5120 elems per A split
    const int BOFF = BK * SBP;                  // 2304 elems per B split
    const int STAGE_E = 2 * AOFF + 2 * BOFF;    // 14848 elems

    float acc[2][4][4];
#pragma unroll
    for (int i = 0; i < 2; i++)
#pragma unroll
        for (int j = 0; j < 4; j++)
#pragma unroll
            for (int k = 0; k < 4; k++) acc[i][j][k] = 0.f;

    auto load_stage = [&](int ks, int buf) {
        const int k0 = ks * BK;
        __nv_bfloat16* base = sm + buf * STAGE_E;
        // A: 128 rows x 32 k-elems, 512 slots of 8 elems, 2 per thread (x2 splits)
#pragma unroll
        for (int i = 0; i < 2; i++) {
            int c = tid + i * 256;
            int row = c >> 2, seg = c & 3;
            const __nv_bfloat16* gh = g_Ah + (size_t)(rowBase + row) * F1 + k0 + seg * 8;
            const __nv_bfloat16* gl = g_Al + (size_t)(rowBase + row) * F1 + k0 + seg * 8;
            cp16(su32(base + row * SAP + seg * 8), gh);
            cp16(su32(base + AOFF + row * SAP + seg * 8), gl);
        }
        // B: 32 k-rows x 64 cols, 256 slots of 8 elems, 1 per thread (x2 splits)
        {
            int kr = tid >> 3, seg = tid & 7;
            const __nv_bfloat16* gh = g_Bh + (size_t)(k0 + kr) * NPAD + nBase + seg * 8;
            const __nv_bfloat16* gl = g_Bl + (size_t)(k0 + kr) * NPAD + nBase + seg * 8;
            cp16(su32(base + 2 * AOFF + kr * SBP + seg * 8), gh);
            cp16(su32(base + 2 * AOFF + BOFF + kr * SBP + seg * 8), gl);
        }
        cp_commit();
    };

    const int grp = lane >> 3, lr = lane & 7;

    auto compute_stage = [&](int buf) {
        __nv_bfloat16* base = sm + buf * STAGE_E;
#pragma unroll
        for (int kk = 0; kk < 2; kk++) {
            unsigned afh[2][4], afl[2][4], bfh[2][4], bfl[2][4];
            int acol = kk * 16 + (grp >> 1) * 8;
#pragma unroll
            for (int mt = 0; mt < 2; mt++) {
                int arow = wm * 32 + mt * 16 + (grp & 1) * 8 + lr;
                ldsm_x4(afh[mt], su32(base + arow * SAP + acol));
                ldsm_x4(afl[mt], su32(base + AOFF + arow * SAP + acol));
            }
            int krow = kk * 16 + (grp & 1) * 8 + lr;
#pragma unroll
            for (int np = 0; np < 2; np++) {
                int ncol = wn * 32 + np * 16 + (grp >> 1) * 8;
                ldsm_x4_t(bfh[np], su32(base + 2 * AOFF + krow * SBP + ncol));
                ldsm_x4_t(bfl[np], su32(base + 2 * AOFF + BOFF + krow * SBP + ncol));
            }
#pragma unroll
            for (int mt = 0; mt < 2; mt++)
#pragma unroll
                for (int nt = 0; nt < 4; nt++) {
                    const unsigned* bh = &bfh[nt >> 1][(nt & 1) * 2];
                    const unsigned* bl = &bfl[nt >> 1][(nt & 1) * 2];
                    mma_bf16(acc[mt][nt], afh[mt], bh);
                    mma_bf16(acc[mt][nt], afh[mt], bl);
                    mma_bf16(acc[mt][nt], afl[mt], bh);
                }
        }
    };

    load_stage(0, 0);
    for (int ks = 0; ks < NKITER; ks++) {
        if (ks + 1 < NKITER) {
            load_stage(ks + 1, (ks + 1) & 1);
            cp_wait<1>();
        } else {
            cp_wait<0>();
        }
        __syncthreads();
        compute_stage(ks & 1);
        __syncthreads();
    }

#pragma unroll
    for (int mt = 0; mt < 2; mt++) {
#pragma unroll
        for (int nt = 0; nt < 4; nt++) {
            int row0 = rowBase + wm * 32 + mt * 16 + (lane >> 2);
            int col0 = nBase + wn * 32 + nt * 8 + (lane & 3) * 2;
            float* a = acc[mt][nt];
            if (col0 < F1) {
                float bsum0 = bias[col0];
                float bsum1 = (col0 + 1 < F1) ? bias[col0 + 1] : 0.f;
                if (row0 < NN) {
                    float v0 = a[0] + bsum0;
                    g_hid[(long)row0 * F1 + col0] = v0 > 0.f ? v0 : 0.f;
                    if (col0 + 1 < F1) {
                        float v1 = a[1] + bsum1;
                        g_hid[(long)row0 * F1 + col0 + 1] = v1 > 0.f ? v1 : 0.f;
                    }
                }
                if (row0 + 8 < NN) {
                    float v2 = a[2] + bsum0;
                    g_hid[(long)(row0 + 8) * F1 + col0] = v2 > 0.f ? v2 : 0.f;
                    if (col0 + 1 < F1) {
                        float v3 = a[3] + bsum1;
                        g_hid[(long)(row0 + 8) * F1 + col0 + 1] = v3 > 0.f ? v3 : 0.f;
                    }
                }
            }
        }
    }
}

// out = g_hid[20000,800] @ W2[800,5] + b2. One warp per row.
__global__ void k_gemm2(const float* __restrict__ W2, const float* __restrict__ b2,
                        float* __restrict__ out) {
    long w = ((long)blockIdx.x * blockDim.x + threadIdx.x) >> 5;
    int lane = threadIdx.x & 31;
    if (w >= NN) return;
    const float* hr = g_hid + w * F1;
    float a0 = 0.f, a1 = 0.f, a2 = 0.f, a3 = 0.f, a4 = 0.f;
    for (int k4 = lane * 4; k4 < F1; k4 += 128) {
        float4 hv = *(const float4*)(hr + k4);
        float hs[4] = {hv.x, hv.y, hv.z, hv.w};
#pragma unroll
        for (int t = 0; t < 4; t++) {
            const float* wv = W2 + (k4 + t) * 5;
            float hk = hs[t];
            a0 += hk * wv[0];
            a1 += hk * wv[1];
            a2 += hk * wv[2];
            a3 += hk * wv[3];
            a4 += hk * wv[4];
        }
    }
#pragma unroll
    for (int o = 16; o; o >>= 1) {
        a0 += __shfl_xor_sync(0xffffffffu, a0, o);
        a1 += __shfl_xor_sync(0xffffffffu, a1, o);
        a2 += __shfl_xor_sync(0xffffffffu, a2, o);
        a3 += __shfl_xor_sync(0xffffffffu, a3, o);
        a4 += __shfl_xor_sync(0xffffffffu, a4, o);
    }
    if (lane == 0) {
        out[w * 5 + 0] = a0 + b2[0];
        out[w * 5 + 1] = a1 + b2[1];
        out[w * 5 + 2] = a2 + b2[2];
        out[w * 5 + 3] = a3 + b2[3];
        out[w * 5 + 4] = a4 + b2[4];
    }
}

// ---------------- launcher ----------------------------------------------------
extern "C" void kernel_launch(void* const* d_in, const int* in_sizes, int n_in,
                              void* d_out, int out_size) {
    const float* x     = (const float*)d_in[0];
    const int*   ei    = (const int*)d_in[1];
    const float* ew    = (const float*)d_in[2];
    const float* Wl    = (const float*)d_in[3];
    const float* bl    = (const float*)d_in[4];
    const float* Wr    = (const float*)d_in[5];
    const float* br    = (const float*)d_in[6];
    const float* We    = (const float*)d_in[7];
    const float* att   = (const float*)d_in[8];
    const float* cb    = (const float*)d_in[9];
    const float* gamma = (const float*)d_in[10];
    const float* beta  = (const float*)d_in[11];
    const float* W1    = (const float*)d_in[12];
    const float* b1    = (const float*)d_in[13];
    const float* W2    = (const float*)d_in[14];
    const float* b2    = (const float*)d_in[15];
    float* out = (float*)d_out;

    const int SMEM_BYTES = 2 * (2 * BM * SAP + 2 * BK * SBP) * (int)sizeof(__nv_bfloat16);
    cudaFuncSetAttribute(k_gemm1, cudaFuncAttributeMaxDynamicSharedMemorySize, SMEM_BYTES);

    k_init<<<4096, 256>>>();                                          // 0
    {   // xl/xr                                                        1
        long total = (long)LNUM * NN * HC;
        k_xlxr<<<(int)((total + 255) / 256), 256>>>(x, Wl, bl, Wr, br);
    }
    {   // degrees                                                      2
        long total = (long)LNUM * EE;
        k_deg<<<(int)((total + 255) / 256), 256>>>(ei, ew);
    }
    {   // fused edge pass (inline self-loop attr)                      3 (ncu target)
        dim3 grid(EGX, LNUM);
        k_edge<<<grid, 256>>>(ei, ew, We, att);
    }
    {   // node pass                                                    4
        dim3 grid(LNUM, 10);
        dim3 block(32, 8);
        k_node<<<grid, block>>>(cb);
    }
    {   // W1 split                                                     5
        long total = (long)F1 * NPAD;
        k_cvtW1<<<(int)((total + 255) / 256), 256>>>(W1);
    }
    {   // BN finalize + A-operand bf16 split                           6
        long total = (long)MPAD * F1;
        k_bnfin<<<(int)((total + 255) / 256), 256>>>(gamma, beta);
    }
    {   // MLP layer 1 (tensor cores, 128x64 tiles)                     7
        dim3 grid(NPAD / BN, MPAD / BM);
        k_gemm1<<<grid, 256, SMEM_BYTES>>>(b1);
    }
    {   // MLP layer 2                                                  8
        long threads = (long)NN * 32;
        k_gemm2<<<(int)((threads + 255) / 256), 256>>>(W2, b2, out);
    }
    (void)in_sizes; (void)n_in; (void)out_size;
}

// round 12
// speedup vs baseline: 1.7743x; 1.1723x over previous
#include <cuda_runtime.h>
#include <cuda_bf16.h>
#include <cuda_fp16.h>
#include <math.h>

// Problem constants
#define LNUM 25
#define NN   20000
#define EE   100000
#define ENE  120000      // EE + NN (with self loops)
#define CC   32
#define HH   2
#define HC   64          // HH*CC
#define F1   800         // LNUM*CC
#define BNEPS 1e-5f

// GEMM1 tiling: 128x64 blocks, fp16 2-split mma.sync
#define MPAD 20096       // 157 * 128
#define NPAD 832         // 13 * 64
#define BM 128
#define BN 64
#define BK 32
#define SAP 40           // A smem pitch (elems): 80B rows
#define SBP 72           // B smem pitch (elems): 144B rows
#define NKITER (F1 / BK) // 25

// edge kernel grid
#define EGX 250                       // blocks per layer
#define NHW (EGX * 256 / 16)          // 4000 half-warps per layer
#define EITER (ENE / NHW)             // 30 (exact)

// ---------------- scratch (device globals; no allocation allowed) -------------
__device__ float  g_xl[LNUM * NN * HC];
__device__ float  g_xr[LNUM * NN * HC];
__device__ float  g_degw[LNUM * NN * 2];     // (cnt, wsum) interleaved
__device__ float  g_denom[LNUM * NN * 2];
__device__ float  g_num[LNUM * NN * HC];
__device__ double g_bnsum[LNUM * CC];
__device__ double g_bnsq[LNUM * CC];
__device__ float  g_bnscale[F1];
__device__ float  g_bnshift[F1];
__device__ float  g_h[NN * F1];              // concat features pre-BN
__device__ float  g_hid[NN * F1];            // MLP hidden (fp32)
__device__ __half g_Ah[(size_t)MPAD * F1];
__device__ __half g_Al[(size_t)MPAD * F1];
__device__ __half g_Bh[(size_t)F1 * NPAD];

// ---------------- helpers -----------------------------------------------------
__device__ __forceinline__ void redAddV4(float* p, float a, float b, float c, float d) {
    asm volatile("red.global.add.v4.f32 [%0], {%1,%2,%3,%4};"
                 :: "l"(p), "f"(a), "f"(b), "f"(c), "f"(d) : "memory");
}
__device__ __forceinline__ void redAddV2(float* p, float a, float b) {
    asm volatile("red.global.add.v2.f32 [%0], {%1,%2};"
                 :: "l"(p), "f"(a), "f"(b) : "memory");
}
__device__ __forceinline__ unsigned su32(const void* p) {
    return (unsigned)__cvta_generic_to_shared(p);
}
__device__ __forceinline__ void cp16(unsigned s, const void* g) {
    asm volatile("cp.async.cg.shared.global [%0], [%1], 16;" :: "r"(s), "l"(g));
}
__device__ __forceinline__ void cp_commit() { asm volatile("cp.async.commit_group;"); }
template<int N> __device__ __forceinline__ void cp_wait() {
    asm volatile("cp.async.wait_group %0;" :: "n"(N));
}
__device__ __forceinline__ void ldsm_x4(unsigned* r, unsigned addr) {
    asm volatile("ldmatrix.sync.aligned.m8n8.x4.shared.b16 {%0,%1,%2,%3}, [%4];"
                 : "=r"(r[0]), "=r"(r[1]), "=r"(r[2]), "=r"(r[3]) : "r"(addr));
}
__device__ __forceinline__ void ldsm_x4_t(unsigned* r, unsigned addr) {
    asm volatile("ldmatrix.sync.aligned.m8n8.x4.trans.shared.b16 {%0,%1,%2,%3}, [%4];"
                 : "=r"(r[0]), "=r"(r[1]), "=r"(r[2]), "=r"(r[3]) : "r"(addr));
}
__device__ __forceinline__ void mma_f16(float* d, const unsigned* a, const unsigned* b) {
    asm volatile("mma.sync.aligned.m16n8k16.row.col.f32.f16.f16.f32 "
                 "{%0,%1,%2,%3}, {%4,%5,%6,%7}, {%8,%9}, {%0,%1,%2,%3};"
                 : "+f"(d[0]), "+f"(d[1]), "+f"(d[2]), "+f"(d[3])
                 : "r"(a[0]), "r"(a[1]), "r"(a[2]), "r"(a[3]), "r"(b[0]), "r"(b[1]));
}

// ---------------- kernels ------------------------------------------------------

__global__ void k_init() {
    long i0 = (long)blockIdx.x * blockDim.x + threadIdx.x;
    long st = (long)gridDim.x * blockDim.x;
    for (long t = i0; t < (long)LNUM * NN * HC; t += st) g_num[t] = 0.f;
    for (long t = i0; t < (long)LNUM * NN * 2; t += st) { g_denom[t] = 0.f; g_degw[t] = 0.f; }
    for (long t = i0; t < (long)LNUM * CC; t += st) { g_bnsum[t] = 0.0; g_bnsq[t] = 0.0; }
}

// xl = x@Wl + bl ; xr = x@Wr + br
__global__ void k_xlxr(const float* __restrict__ x,
                       const float* __restrict__ Wl, const float* __restrict__ bl,
                       const float* __restrict__ Wr, const float* __restrict__ br) {
    long idx = (long)blockIdx.x * blockDim.x + threadIdx.x;
    if (idx >= (long)LNUM * NN * HC) return;
    int j = (int)(idx % HC);
    long r = idx / HC;
    int n = (int)(r % NN);
    int l = (int)(r / NN);
    const float* xv = x + (long)n * 5;
    float accl = bl[l * HC + j];
    float accr = br[l * HC + j];
#pragma unroll
    for (int k = 0; k < 5; k++) {
        float xk = xv[k];
        accl += xk * Wl[((long)l * 5 + k) * HC + j];
        accr += xk * Wr[((long)l * 5 + k) * HC + j];
    }
    g_xl[idx] = accl;
    g_xr[idx] = accr;
}

// in-degree + sum of incoming weights via one v2 reduction per edge
__global__ void k_deg(const int* __restrict__ ei, const float* __restrict__ ew) {
    long idx = (long)blockIdx.x * blockDim.x + threadIdx.x;
    if (idx >= (long)LNUM * EE) return;
    int e = (int)(idx % EE);
    int l = (int)(idx / EE);
    int d = __ldg(&ei[((long)l * 2 + 1) * EE + e]);
    redAddV2(&g_degw[((long)l * NN + d) * 2], 1.0f, __ldg(&ew[(long)l * EE + e]));
}

// FUSED edge pass.  2D grid: blockIdx.y = layer.  Each half-warp handles
// EITER=30 edges with stride NHW (exact => uniform control flow; iters 25-29
// are uniformly self loops with attr = wsum/max(cnt,1) from g_degw).
__global__ void __launch_bounds__(256) k_edge(const int* __restrict__ ei,
                                              const float* __restrict__ ew,
                                              const float* __restrict__ We,
                                              const float* __restrict__ att) {
    const int l = blockIdx.y;
    const int lane = threadIdx.x & 31;
    const int sub = lane & 15;
    const int j = sub * 4;
    const int hw0 = (blockIdx.x * 256 + threadIdx.x) >> 4;

    const float4 we4 = *(const float4*)&We[l * HC + j];
    const float4 at4 = *(const float4*)&att[l * HC + j];
    const int*   srcp = ei + (long)l * 2 * EE;
    const int*   dstp = srcp + EE;
    const float* ewp  = ew + (long)l * EE;
    const float* xlL  = g_xl + (long)l * NN * HC;
    const float* xrL  = g_xr + (long)l * NN * HC;
    const float* degwL = g_degw + (long)l * NN * 2;
    float* denomL = g_denom + (long)l * NN * 2;
    float* numL   = g_num + (long)l * NN * HC;

#pragma unroll 2
    for (int it = 0; it < EITER; it++) {
        int e = hw0 + it * NHW;
        int s, d; float w;
        if (e < EE) {
            s = __ldg(srcp + e);
            d = __ldg(dstp + e);
            w = __ldg(ewp + e);
        } else {
            s = e - EE; d = s;
            float2 dw = *(const float2*)&degwL[(long)s * 2];
            w = dw.y / fmaxf(dw.x, 1.0f);
        }
        const float4 xl4 = *(const float4*)&xlL[(long)s * HC + j];
        const float4 xr4 = *(const float4*)&xrL[(long)d * HC + j];
        float t0 = xl4.x + xr4.x + w * we4.x;
        float t1 = xl4.y + xr4.y + w * we4.y;
        float t2 = xl4.z + xr4.z + w * we4.z;
        float t3 = xl4.w + xr4.w + w * we4.w;
        t0 = t0 > 0.f ? t0 : 0.2f * t0;
        t1 = t1 > 0.f ? t1 : 0.2f * t1;
        t2 = t2 > 0.f ? t2 : 0.2f * t2;
        t3 = t3 > 0.f ? t3 : 0.2f * t3;
        float v = t0 * at4.x + t1 * at4.y + t2 * at4.z + t3 * at4.w;
        v += __shfl_xor_sync(0xffffffffu, v, 1);
        v += __shfl_xor_sync(0xffffffffu, v, 2);
        v += __shfl_xor_sync(0xffffffffu, v, 4);
        float vother = __shfl_sync(0xffffffffu, v, (lane & 16) | 8);
        float p  = __expf(v);
        float p1 = __expf(vother);
        if (sub == 0) {
            redAddV2(&denomL[(long)d * 2], p, p1);
        }
        redAddV4(&numL[(long)d * HC + j],
                 xl4.x * p, xl4.y * p, xl4.z * p, xl4.w * p);
    }
}

// Node pass: normalize, head-mean, conv bias, concat layout write, BN partials.
__global__ void k_node(const float* __restrict__ conv_bias) {
    int l = blockIdx.x;
    int c = threadIdx.x;
    int ty = threadIdx.y;
    int base = blockIdx.y * 2000;
    float cb = conv_bias[l * CC + c];
    float s1 = 0.f, s2 = 0.f;
    for (int n = base + ty; n < base + 2000; n += 8) {
        float2 den = *(const float2*)&g_denom[((long)l * NN + n) * 2];
        float deg  = g_degw[((long)l * NN + n) * 2] + 1.0f;
        long nb = ((long)l * NN + n) * HC;
        float o = 0.5f * (g_num[nb + c] / den.x + g_num[nb + 32 + c] / den.y) / deg + cb;
        g_h[(long)n * F1 + l * CC + c] = o;
        s1 += o;
        s2 += o * o;
    }
    __shared__ float sm1[8][32];
    __shared__ float sm2[8][32];
    sm1[ty][c] = s1; sm2[ty][c] = s2;
    __syncthreads();
    if (ty == 0) {
        float t1 = 0.f, t2 = 0.f;
#pragma unroll
        for (int y = 0; y < 8; y++) { t1 += sm1[y][c]; t2 += sm2[y][c]; }
        atomicAdd(&g_bnsum[l * CC + c], (double)t1);
        atomicAdd(&g_bnsq[l * CC + c], (double)t2);
    }
}

// Tiny: turn BN sums into per-feature scale/shift (800 threads, one block wave)
__global__ void k_bnstat(const float* __restrict__ gamma1, const float* __restrict__ beta1) {
    int f = blockIdx.x * blockDim.x + threadIdx.x;
    if (f >= F1) return;
    double mean = g_bnsum[f] * (1.0 / NN);
    double var  = g_bnsq[f] * (1.0 / NN) - mean * mean;
    float inv = rsqrtf((float)var + BNEPS);
    float sc = gamma1[f] * inv;
    g_bnscale[f] = sc;
    g_bnshift[f] = beta1[f] - sc * (float)mean;
}

// BN finalize + leaky(0.01) + fp16 hi/lo split into GEMM A operand (padded rows).
__global__ void k_bnfin() {
    long idx = (long)blockIdx.x * blockDim.x + threadIdx.x;
    if (idx >= (long)MPAD * F1) return;
    int f = (int)(idx % F1);
    long row = idx / F1;
    float o = 0.f;
    if (row < NN) {
        o = g_bnscale[f] * g_h[idx] + g_bnshift[f];
        o = o > 0.f ? o : 0.01f * o;
    }
    __half hi = __float2half_rn(o);
    __half lo = __float2half_rn(o - __half2float(hi));
    g_Ah[idx] = hi;
    g_Al[idx] = lo;
}

// W1 -> fp16 (round-to-nearest, residual |Bl| <= 2^-12|B| dropped), N padded to 832
__global__ void k_cvtW1(const float* __restrict__ W1) {
    long idx = (long)blockIdx.x * blockDim.x + threadIdx.x;
    if (idx >= (long)F1 * NPAD) return;
    int n = (int)(idx % NPAD);
    int k = (int)(idx / NPAD);
    float v = (n < F1) ? W1[(long)k * F1 + n] : 0.f;
    g_Bh[idx] = __float2half_rn(v);
}

// GEMM1: g_hid = relu(A[20000,800] @ W1[800,800] + b1), fp16 2-split mma.sync.
// D = Ah*Bh + Al*Bh.  128x64 block tile, 8 warps of 32x32.
__global__ void __launch_bounds__(256, 2) k_gemm1(const float* __restrict__ bias) {
    extern __shared__ __half sm[];
    const int tid = threadIdx.x;
    const int wid = tid >> 5, lane = tid & 31;
    const int wm = wid >> 1, wn = wid & 1;      // 4 x 2 warp grid, 32x32 per warp
    const int rowBase = blockIdx.y * BM, nBase = blockIdx.x * BN;

    const int AOFF = BM * SAP;                  // 5120 elems per A split
    const int BOFF = BK * SBP;                  // 2304 elems
    const int STAGE_E = 2 * AOFF + BOFF;        // 12544 elems

    float acc[2][4][4];
#pragma unroll
    for (int i = 0; i < 2; i++)
#pragma unroll
        for (int j = 0; j < 4; j++)
#pragma unroll
            for (int k = 0; k < 4; k++) acc[i][j][k] = 0.f;

    auto load_stage = [&](int ks, int buf) {
        const int k0 = ks * BK;
        __half* base = sm + buf * STAGE_E;
        // A: 128 rows x 32 k-elems, 512 slots of 8 elems, 2 per thread (x2 splits)
#pragma unroll
        for (int i = 0; i < 2; i++) {
            int c = tid + i * 256;
            int row = c >> 2, seg = c & 3;
            const __half* gh = g_Ah + (size_t)(rowBase + row) * F1 + k0 + seg * 8;
            const __half* gl = g_Al + (size_t)(rowBase + row) * F1 + k0 + seg * 8;
            cp16(su32(base + row * SAP + seg * 8), gh);
            cp16(su32(base + AOFF + row * SAP + seg * 8), gl);
        }
        // B: 32 k-rows x 64 cols, 256 slots of 8 elems, 1 per thread
        {
            int kr = tid >> 3, seg = tid & 7;
            const __half* gh = g_Bh + (size_t)(k0 + kr) * NPAD + nBase + seg * 8;
            cp16(su32(base + 2 * AOFF + kr * SBP + seg * 8), gh);
        }
        cp_commit();
    };

    const int grp = lane >> 3, lr = lane & 7;

    auto compute_stage = [&](int buf) {
        __half* base = sm + buf * STAGE_E;
#pragma unroll
        for (int kk = 0; kk < 2; kk++) {
            unsigned afh[2][4], afl[2][4], bf[2][4];
            int acol = kk * 16 + (grp >> 1) * 8;
#pragma unroll
            for (int mt = 0; mt < 2; mt++) {
                int arow = wm * 32 + mt * 16 + (grp & 1) * 8 + lr;
                ldsm_x4(afh[mt], su32(base + arow * SAP + acol));
                ldsm_x4(afl[mt], su32(base + AOFF + arow * SAP + acol));
            }
            int krow = kk * 16 + (grp & 1) * 8 + lr;
#pragma unroll
            for (int np = 0; np < 2; np++) {
                int ncol = wn * 32 + np * 16 + (grp >> 1) * 8;
                ldsm_x4_t(bf[np], su32(base + 2 * AOFF + krow * SBP + ncol));
            }
#pragma unroll
            for (int mt = 0; mt < 2; mt++)
#pragma unroll
                for (int nt = 0; nt < 4; nt++) {
                    const unsigned* b = &bf[nt >> 1][(nt & 1) * 2];
                    mma_f16(acc[mt][nt], afh[mt], b);
                    mma_f16(acc[mt][nt], afl[mt], b);
                }
        }
    };

    load_stage(0, 0);
    for (int ks = 0; ks < NKITER; ks++) {
        if (ks + 1 < NKITER) {
            load_stage(ks + 1, (ks + 1) & 1);
            cp_wait<1>();
        } else {
            cp_wait<0>();
        }
        __syncthreads();
        compute_stage(ks & 1);
        __syncthreads();
    }

#pragma unroll
    for (int mt = 0; mt < 2; mt++) {
#pragma unroll
        for (int nt = 0; nt < 4; nt++) {
            int row0 = rowBase + wm * 32 + mt * 16 + (lane >> 2);
            int col0 = nBase + wn * 32 + nt * 8 + (lane & 3) * 2;
            float* a = acc[mt][nt];
            if (col0 < F1) {
                float bsum0 = bias[col0];
                float bsum1 = (col0 + 1 < F1) ? bias[col0 + 1] : 0.f;
                if (row0 < NN) {
                    float v0 = a[0] + bsum0;
                    g_hid[(long)row0 * F1 + col0] = v0 > 0.f ? v0 : 0.f;
                    if (col0 + 1 < F1) {
                        float v1 = a[1] + bsum1;
                        g_hid[(long)row0 * F1 + col0 + 1] = v1 > 0.f ? v1 : 0.f;
                    }
                }
                if (row0 + 8 < NN) {
                    float v2 = a[2] + bsum0;
                    g_hid[(long)(row0 + 8) * F1 + col0] = v2 > 0.f ? v2 : 0.f;
                    if (col0 + 1 < F1) {
                        float v3 = a[3] + bsum1;
                        g_hid[(long)(row0 + 8) * F1 + col0 + 1] = v3 > 0.f ? v3 : 0.f;
                    }
                }
            }
        }
    }
}

// out = g_hid[20000,800] @ W2[800,5] + b2. One warp per row.
__global__ void k_gemm2(const float* __restrict__ W2, const float* __restrict__ b2,
                        float* __restrict__ out) {
    long w = ((long)blockIdx.x * blockDim.x + threadIdx.x) >> 5;
    int lane = threadIdx.x & 31;
    if (w >= NN) return;
    const float* hr = g_hid + w * F1;
    float a0 = 0.f, a1 = 0.f, a2 = 0.f, a3 = 0.f, a4 = 0.f;
    for (int k4 = lane * 4; k4 < F1; k4 += 128) {
        float4 hv = *(const float4*)(hr + k4);
        float hs[4] = {hv.x, hv.y, hv.z, hv.w};
#pragma unroll
        for (int t = 0; t < 4; t++) {
            const float* wv = W2 + (k4 + t) * 5;
            float hk = hs[t];
            a0 += hk * wv[0];
            a1 += hk * wv[1];
            a2 += hk * wv[2];
            a3 += hk * wv[3];
            a4 += hk * wv[4];
        }
    }
#pragma unroll
    for (int o = 16; o; o >>= 1) {
        a0 += __shfl_xor_sync(0xffffffffu, a0, o);
        a1 += __shfl_xor_sync(0xffffffffu, a1, o);
        a2 += __shfl_xor_sync(0xffffffffu, a2, o);
        a3 += __shfl_xor_sync(0xffffffffu, a3, o);
        a4 += __shfl_xor_sync(0xffffffffu, a4, o);
    }
    if (lane == 0) {
        out[w * 5 + 0] = a0 + b2[0];
        out[w * 5 + 1] = a1 + b2[1];
        out[w * 5 + 2] = a2 + b2[2];
        out[w * 5 + 3] = a3 + b2[3];
        out[w * 5 + 4] = a4 + b2[4];
    }
}

// ---------------- launcher ----------------------------------------------------
extern "C" void kernel_launch(void* const* d_in, const int* in_sizes, int n_in,
                              void* d_out, int out_size) {
    const float* x     = (const float*)d_in[0];
    const int*   ei    = (const int*)d_in[1];
    const float* ew    = (const float*)d_in[2];
    const float* Wl    = (const float*)d_in[3];
    const float* bl    = (const float*)d_in[4];
    const float* Wr    = (const float*)d_in[5];
    const float* br    = (const float*)d_in[6];
    const float* We    = (const float*)d_in[7];
    const float* att   = (const float*)d_in[8];
    const float* cb    = (const float*)d_in[9];
    const float* gamma = (const float*)d_in[10];
    const float* beta  = (const float*)d_in[11];
    const float* W1    = (const float*)d_in[12];
    const float* b1    = (const float*)d_in[13];
    const float* W2    = (const float*)d_in[14];
    const float* b2    = (const float*)d_in[15];
    float* out = (float*)d_out;

    const int SMEM_BYTES = 2 * (2 * BM * SAP + BK * SBP) * (int)sizeof(__half);
    cudaFuncSetAttribute(k_gemm1, cudaFuncAttributeMaxDynamicSharedMemorySize, SMEM_BYTES);

    k_init<<<4096, 256>>>();                                          // 0
    {   // xl/xr                                                        1
        long total = (long)LNUM * NN * HC;
        k_xlxr<<<(int)((total + 255) / 256), 256>>>(x, Wl, bl, Wr, br);
    }
    {   // degrees                                                      2
        long total = (long)LNUM * EE;
        k_deg<<<(int)((total + 255) / 256), 256>>>(ei, ew);
    }
    {   // fused edge pass (inline self-loop attr)                      3 (ncu target)
        dim3 grid(EGX, LNUM);
        k_edge<<<grid, 256>>>(ei, ew, We, att);
    }
    {   // node pass                                                    4
        dim3 grid(LNUM, 10);
        dim3 block(32, 8);
        k_node<<<grid, block>>>(cb);
    }
    {   // W1 -> fp16                                                   5
        long total = (long)F1 * NPAD;
        k_cvtW1<<<(int)((total + 255) / 256), 256>>>(W1);
    }
    {   // BN scale/shift                                               6
        k_bnstat<<<(F1 + 255) / 256, 256>>>(gamma, beta);
    }
    {   // BN finalize + A-operand fp16 split                           7
        long total = (long)MPAD * F1;
        k_bnfin<<<(int)((total + 255) / 256), 256>>>();
    }
    {   // MLP layer 1 (fp16 2-split tensor cores)                      8
        dim3 grid(NPAD / BN, MPAD / BM);
        k_gemm1<<<grid, 256, SMEM_BYTES>>>(b1);
    }
    {   // MLP layer 2                                                  9
        long threads = (long)NN * 32;
        k_gemm2<<<(int)((threads + 255) / 256), 256>>>(W2, b2, out);
    }
    (void)in_sizes; (void)n_in; (void)out_size;
}

// round 13
// speedup vs baseline: 1.9275x; 1.0863x over previous
#include <cuda_runtime.h>
#include <cuda_bf16.h>
#include <cuda_fp16.h>
#include <math.h>

// Problem constants
#define LNUM 25
#define NN   20000
#define EE   100000
#define ENE  120000      // EE + NN (with self loops)
#define CC   32
#define HH   2
#define HC   64          // HH*CC
#define F1   800         // LNUM*CC
#define BNEPS 1e-5f

// GEMM1 tiling: 128x64 blocks, plain fp16 mma.sync (fp32 accum)
#define MPAD 20096       // 157 * 128
#define NPAD 832         // 13 * 64
#define BM 128
#define BN 64
#define BK 32
#define SAP 40           // A smem pitch (elems): 80B rows
#define SBP 72           // B smem pitch (elems): 144B rows
#define NKITER (F1 / BK) // 25

// edge kernel grid
#define EGX 250                       // blocks per layer
#define NHW (EGX * 256 / 16)          // 4000 half-warps per layer
#define EITER (ENE / NHW)             // 30 (exact)

// ---------------- scratch (device globals; no allocation allowed) -------------
__device__ float  g_xl[LNUM * NN * HC];
__device__ float  g_xr[LNUM * NN * HC];
__device__ float  g_degw[LNUM * NN * 2];     // (cnt, wsum) interleaved
__device__ float  g_denom[LNUM * NN * 2];
__device__ float  g_num[LNUM * NN * HC];
__device__ double g_bnsum[LNUM * CC];
__device__ double g_bnsq[LNUM * CC];
__device__ float  g_bnscale[F1];
__device__ float  g_bnshift[F1];
__device__ float  g_h[NN * F1];              // concat features pre-BN
__device__ float  g_hid[NN * F1];            // MLP hidden (fp32)
__device__ __half g_Ah[(size_t)MPAD * F1];
__device__ __half g_Bh[(size_t)F1 * NPAD];

// ---------------- helpers -----------------------------------------------------
__device__ __forceinline__ void redAddV4(float* p, float a, float b, float c, float d) {
    asm volatile("red.global.add.v4.f32 [%0], {%1,%2,%3,%4};"
                 :: "l"(p), "f"(a), "f"(b), "f"(c), "f"(d) : "memory");
}
__device__ __forceinline__ void redAddV2(float* p, float a, float b) {
    asm volatile("red.global.add.v2.f32 [%0], {%1,%2};"
                 :: "l"(p), "f"(a), "f"(b) : "memory");
}
__device__ __forceinline__ unsigned su32(const void* p) {
    return (unsigned)__cvta_generic_to_shared(p);
}
__device__ __forceinline__ void cp16(unsigned s, const void* g) {
    asm volatile("cp.async.cg.shared.global [%0], [%1], 16;" :: "r"(s), "l"(g));
}
__device__ __forceinline__ void cp_commit() { asm volatile("cp.async.commit_group;"); }
template<int N> __device__ __forceinline__ void cp_wait() {
    asm volatile("cp.async.wait_group %0;" :: "n"(N));
}
__device__ __forceinline__ void ldsm_x4(unsigned* r, unsigned addr) {
    asm volatile("ldmatrix.sync.aligned.m8n8.x4.shared.b16 {%0,%1,%2,%3}, [%4];"
                 : "=r"(r[0]), "=r"(r[1]), "=r"(r[2]), "=r"(r[3]) : "r"(addr));
}
__device__ __forceinline__ void ldsm_x4_t(unsigned* r, unsigned addr) {
    asm volatile("ldmatrix.sync.aligned.m8n8.x4.trans.shared.b16 {%0,%1,%2,%3}, [%4];"
                 : "=r"(r[0]), "=r"(r[1]), "=r"(r[2]), "=r"(r[3]) : "r"(addr));
}
__device__ __forceinline__ void mma_f16(float* d, const unsigned* a, const unsigned* b) {
    asm volatile("mma.sync.aligned.m16n8k16.row.col.f32.f16.f16.f32 "
                 "{%0,%1,%2,%3}, {%4,%5,%6,%7}, {%8,%9}, {%0,%1,%2,%3};"
                 : "+f"(d[0]), "+f"(d[1]), "+f"(d[2]), "+f"(d[3])
                 : "r"(a[0]), "r"(a[1]), "r"(a[2]), "r"(a[3]), "r"(b[0]), "r"(b[1]));
}

// ---------------- kernels ------------------------------------------------------

__global__ void k_init() {
    long i0 = (long)blockIdx.x * blockDim.x + threadIdx.x;
    long st = (long)gridDim.x * blockDim.x;
    for (long t = i0; t < (long)LNUM * NN * HC; t += st) g_num[t] = 0.f;
    for (long t = i0; t < (long)LNUM * NN * 2; t += st) { g_denom[t] = 0.f; g_degw[t] = 0.f; }
    for (long t = i0; t < (long)LNUM * CC; t += st) { g_bnsum[t] = 0.0; g_bnsq[t] = 0.0; }
}

// xl = x@Wl + bl ; xr = x@Wr + br
__global__ void k_xlxr(const float* __restrict__ x,
                       const float* __restrict__ Wl, const float* __restrict__ bl,
                       const float* __restrict__ Wr, const float* __restrict__ br) {
    long idx = (long)blockIdx.x * blockDim.x + threadIdx.x;
    if (idx >= (long)LNUM * NN * HC) return;
    int j = (int)(idx % HC);
    long r = idx / HC;
    int n = (int)(r % NN);
    int l = (int)(r / NN);
    const float* xv = x + (long)n * 5;
    float accl = bl[l * HC + j];
    float accr = br[l * HC + j];
#pragma unroll
    for (int k = 0; k < 5; k++) {
        float xk = xv[k];
        accl += xk * Wl[((long)l * 5 + k) * HC + j];
        accr += xk * Wr[((long)l * 5 + k) * HC + j];
    }
    g_xl[idx] = accl;
    g_xr[idx] = accr;
}

// in-degree + sum of incoming weights via one v2 reduction per edge
__global__ void k_deg(const int* __restrict__ ei, const float* __restrict__ ew) {
    long idx = (long)blockIdx.x * blockDim.x + threadIdx.x;
    if (idx >= (long)LNUM * EE) return;
    int e = (int)(idx % EE);
    int l = (int)(idx / EE);
    int d = __ldg(&ei[((long)l * 2 + 1) * EE + e]);
    redAddV2(&g_degw[((long)l * NN + d) * 2], 1.0f, __ldg(&ew[(long)l * EE + e]));
}

// FUSED edge pass.  2D grid: blockIdx.y = layer.  Each half-warp handles
// EITER=30 edges with stride NHW (exact => uniform control flow; iters 25-29
// are uniformly self loops with attr = wsum/max(cnt,1) from g_degw).
__global__ void __launch_bounds__(256) k_edge(const int* __restrict__ ei,
                                              const float* __restrict__ ew,
                                              const float* __restrict__ We,
                                              const float* __restrict__ att) {
    const int l = blockIdx.y;
    const int lane = threadIdx.x & 31;
    const int sub = lane & 15;
    const int j = sub * 4;
    const int hw0 = (blockIdx.x * 256 + threadIdx.x) >> 4;

    const float4 we4 = *(const float4*)&We[l * HC + j];
    const float4 at4 = *(const float4*)&att[l * HC + j];
    const int*   srcp = ei + (long)l * 2 * EE;
    const int*   dstp = srcp + EE;
    const float* ewp  = ew + (long)l * EE;
    const float* xlL  = g_xl + (long)l * NN * HC;
    const float* xrL  = g_xr + (long)l * NN * HC;
    const float* degwL = g_degw + (long)l * NN * 2;
    float* denomL = g_denom + (long)l * NN * 2;
    float* numL   = g_num + (long)l * NN * HC;

#pragma unroll 2
    for (int it = 0; it < EITER; it++) {
        int e = hw0 + it * NHW;
        int s, d; float w;
        if (e < EE) {
            s = __ldg(srcp + e);
            d = __ldg(dstp + e);
            w = __ldg(ewp + e);
        } else {
            s = e - EE; d = s;
            float2 dw = *(const float2*)&degwL[(long)s * 2];
            w = dw.y / fmaxf(dw.x, 1.0f);
        }
        const float4 xl4 = *(const float4*)&xlL[(long)s * HC + j];
        const float4 xr4 = *(const float4*)&xrL[(long)d * HC + j];
        float t0 = xl4.x + xr4.x + w * we4.x;
        float t1 = xl4.y + xr4.y + w * we4.y;
        float t2 = xl4.z + xr4.z + w * we4.z;
        float t3 = xl4.w + xr4.w + w * we4.w;
        t0 = t0 > 0.f ? t0 : 0.2f * t0;
        t1 = t1 > 0.f ? t1 : 0.2f * t1;
        t2 = t2 > 0.f ? t2 : 0.2f * t2;
        t3 = t3 > 0.f ? t3 : 0.2f * t3;
        float v = t0 * at4.x + t1 * at4.y + t2 * at4.z + t3 * at4.w;
        v += __shfl_xor_sync(0xffffffffu, v, 1);
        v += __shfl_xor_sync(0xffffffffu, v, 2);
        v += __shfl_xor_sync(0xffffffffu, v, 4);
        float vother = __shfl_sync(0xffffffffu, v, (lane & 16) | 8);
        float p  = __expf(v);
        float p1 = __expf(vother);
        if (sub == 0) {
            redAddV2(&denomL[(long)d * 2], p, p1);
        }
        redAddV4(&numL[(long)d * HC + j],
                 xl4.x * p, xl4.y * p, xl4.z * p, xl4.w * p);
    }
}

// Node pass: normalize, head-mean, conv bias, concat layout write, BN partials.
__global__ void k_node(const float* __restrict__ conv_bias) {
    int l = blockIdx.x;
    int c = threadIdx.x;
    int ty = threadIdx.y;
    int base = blockIdx.y * 2000;
    float cb = conv_bias[l * CC + c];
    float s1 = 0.f, s2 = 0.f;
    for (int n = base + ty; n < base + 2000; n += 8) {
        float2 den = *(const float2*)&g_denom[((long)l * NN + n) * 2];
        float deg  = g_degw[((long)l * NN + n) * 2] + 1.0f;
        long nb = ((long)l * NN + n) * HC;
        float o = 0.5f * (g_num[nb + c] / den.x + g_num[nb + 32 + c] / den.y) / deg + cb;
        g_h[(long)n * F1 + l * CC + c] = o;
        s1 += o;
        s2 += o * o;
    }
    __shared__ float sm1[8][32];
    __shared__ float sm2[8][32];
    sm1[ty][c] = s1; sm2[ty][c] = s2;
    __syncthreads();
    if (ty == 0) {
        float t1 = 0.f, t2 = 0.f;
#pragma unroll
        for (int y = 0; y < 8; y++) { t1 += sm1[y][c]; t2 += sm2[y][c]; }
        atomicAdd(&g_bnsum[l * CC + c], (double)t1);
        atomicAdd(&g_bnsq[l * CC + c], (double)t2);
    }
}

// Tiny: turn BN sums into per-feature scale/shift
__global__ void k_bnstat(const float* __restrict__ gamma1, const float* __restrict__ beta1) {
    int f = blockIdx.x * blockDim.x + threadIdx.x;
    if (f >= F1) return;
    double mean = g_bnsum[f] * (1.0 / NN);
    double var  = g_bnsq[f] * (1.0 / NN) - mean * mean;
    float inv = rsqrtf((float)var + BNEPS);
    float sc = gamma1[f] * inv;
    g_bnscale[f] = sc;
    g_bnshift[f] = beta1[f] - sc * (float)mean;
}

// BN finalize + leaky(0.01) -> fp16 GEMM A operand (padded rows).
__global__ void k_bnfin() {
    long idx = (long)blockIdx.x * blockDim.x + threadIdx.x;
    if (idx >= (long)MPAD * F1) return;
    int f = (int)(idx % F1);
    long row = idx / F1;
    float o = 0.f;
    if (row < NN) {
        o = g_bnscale[f] * g_h[idx] + g_bnshift[f];
        o = o > 0.f ? o : 0.01f * o;
    }
    g_Ah[idx] = __float2half_rn(o);
}

// W1 -> fp16 (round-to-nearest), N padded to 832
__global__ void k_cvtW1(const float* __restrict__ W1) {
    long idx = (long)blockIdx.x * blockDim.x + threadIdx.x;
    if (idx >= (long)F1 * NPAD) return;
    int n = (int)(idx % NPAD);
    int k = (int)(idx / NPAD);
    float v = (n < F1) ? W1[(long)k * F1 + n] : 0.f;
    g_Bh[idx] = __float2half_rn(v);
}

// GEMM1: g_hid = relu(A[20000,800] @ W1[800,800] + b1), plain fp16 mma.sync,
// fp32 accumulation.  128x64 block tile, 8 warps of 32x32, 3 blocks/SM.
__global__ void __launch_bounds__(256, 3) k_gemm1(const float* __restrict__ bias) {
    extern __shared__ __half sm[];
    const int tid = threadIdx.x;
    const int wid = tid >> 5, lane = tid & 31;
    const int wm = wid >> 1, wn = wid & 1;      // 4 x 2 warp grid, 32x32 per warp
    const int rowBase = blockIdx.y * BM, nBase = blockIdx.x * BN;

    const int AOFF = BM * SAP;                  // 5120 elems
    const int BOFF = BK * SBP;                  // 2304 elems
    const int STAGE_E = AOFF + BOFF;            // 7424 elems (14.5 KB)

    float acc[2][4][4];
#pragma unroll
    for (int i = 0; i < 2; i++)
#pragma unroll
        for (int j = 0; j < 4; j++)
#pragma unroll
            for (int k = 0; k < 4; k++) acc[i][j][k] = 0.f;

    auto load_stage = [&](int ks, int buf) {
        const int k0 = ks * BK;
        __half* base = sm + buf * STAGE_E;
        // A: 128 rows x 32 k-elems = 512 slots of 8 halves, 2 per thread
#pragma unroll
        for (int i = 0; i < 2; i++) {
            int c = tid + i * 256;
            int row = c >> 2, seg = c & 3;
            cp16(su32(base + row * SAP + seg * 8),
                 g_Ah + (size_t)(rowBase + row) * F1 + k0 + seg * 8);
        }
        // B: 32 k-rows x 64 cols = 256 slots of 8 halves, 1 per thread
        {
            int kr = tid >> 3, seg = tid & 7;
            cp16(su32(base + AOFF + kr * SBP + seg * 8),
                 g_Bh + (size_t)(k0 + kr) * NPAD + nBase + seg * 8);
        }
        cp_commit();
    };

    const int grp = lane >> 3, lr = lane & 7;

    auto compute_stage = [&](int buf) {
        __half* base = sm + buf * STAGE_E;
#pragma unroll
        for (int kk = 0; kk < 2; kk++) {
            unsigned af[2][4], bf[2][4];
            int acol = kk * 16 + (grp >> 1) * 8;
#pragma unroll
            for (int mt = 0; mt < 2; mt++) {
                int arow = wm * 32 + mt * 16 + (grp & 1) * 8 + lr;
                ldsm_x4(af[mt], su32(base + arow * SAP + acol));
            }
            int krow = kk * 16 + (grp & 1) * 8 + lr;
#pragma unroll
            for (int np = 0; np < 2; np++) {
                int ncol = wn * 32 + np * 16 + (grp >> 1) * 8;
                ldsm_x4_t(bf[np], su32(base + AOFF + krow * SBP + ncol));
            }
#pragma unroll
            for (int mt = 0; mt < 2; mt++)
#pragma unroll
                for (int nt = 0; nt < 4; nt++) {
                    const unsigned* b = &bf[nt >> 1][(nt & 1) * 2];
                    mma_f16(acc[mt][nt], af[mt], b);
                }
        }
    };

    load_stage(0, 0);
    for (int ks = 0; ks < NKITER; ks++) {
        if (ks + 1 < NKITER) {
            load_stage(ks + 1, (ks + 1) & 1);
            cp_wait<1>();
        } else {
            cp_wait<0>();
        }
        __syncthreads();
        compute_stage(ks & 1);
        __syncthreads();
    }

#pragma unroll
    for (int mt = 0; mt < 2; mt++) {
#pragma unroll
        for (int nt = 0; nt < 4; nt++) {
            int row0 = rowBase + wm * 32 + mt * 16 + (lane >> 2);
            int col0 = nBase + wn * 32 + nt * 8 + (lane & 3) * 2;
            float* a = acc[mt][nt];
            if (col0 < F1) {
                float bsum0 = bias[col0];
                float bsum1 = (col0 + 1 < F1) ? bias[col0 + 1] : 0.f;
                if (row0 < NN) {
                    float v0 = a[0] + bsum0;
                    g_hid[(long)row0 * F1 + col0] = v0 > 0.f ? v0 : 0.f;
                    if (col0 + 1 < F1) {
                        float v1 = a[1] + bsum1;
                        g_hid[(long)row0 * F1 + col0 + 1] = v1 > 0.f ? v1 : 0.f;
                    }
                }
                if (row0 + 8 < NN) {
                    float v2 = a[2] + bsum0;
                    g_hid[(long)(row0 + 8) * F1 + col0] = v2 > 0.f ? v2 : 0.f;
                    if (col0 + 1 < F1) {
                        float v3 = a[3] + bsum1;
                        g_hid[(long)(row0 + 8) * F1 + col0 + 1] = v3 > 0.f ? v3 : 0.f;
                    }
                }
            }
        }
    }
}

// out = g_hid[20000,800] @ W2[800,5] + b2. One warp per row.
__global__ void k_gemm2(const float* __restrict__ W2, const float* __restrict__ b2,
                        float* __restrict__ out) {
    long w = ((long)blockIdx.x * blockDim.x + threadIdx.x) >> 5;
    int lane = threadIdx.x & 31;
    if (w >= NN) return;
    const float* hr = g_hid + w * F1;
    float a0 = 0.f, a1 = 0.f, a2 = 0.f, a3 = 0.f, a4 = 0.f;
    for (int k4 = lane * 4; k4 < F1; k4 += 128) {
        float4 hv = *(const float4*)(hr + k4);
        float hs[4] = {hv.x, hv.y, hv.z, hv.w};
#pragma unroll
        for (int t = 0; t < 4; t++) {
            const float* wv = W2 + (k4 + t) * 5;
            float hk = hs[t];
            a0 += hk * wv[0];
            a1 += hk * wv[1];
            a2 += hk * wv[2];
            a3 += hk * wv[3];
            a4 += hk * wv[4];
        }
    }
#pragma unroll
    for (int o = 16; o; o >>= 1) {
        a0 += __shfl_xor_sync(0xffffffffu, a0, o);
        a1 += __shfl_xor_sync(0xffffffffu, a1, o);
        a2 += __shfl_xor_sync(0xffffffffu, a2, o);
        a3 += __shfl_xor_sync(0xffffffffu, a3, o);
        a4 += __shfl_xor_sync(0xffffffffu, a4, o);
    }
    if (lane == 0) {
        out[w * 5 + 0] = a0 + b2[0];
        out[w * 5 + 1] = a1 + b2[1];
        out[w * 5 + 2] = a2 + b2[2];
        out[w * 5 + 3] = a3 + b2[3];
        out[w * 5 + 4] = a4 + b2[4];
    }
}

// ---------------- launcher ----------------------------------------------------
extern "C" void kernel_launch(void* const* d_in, const int* in_sizes, int n_in,
                              void* d_out, int out_size) {
    const float* x     = (const float*)d_in[0];
    const int*   ei    = (const int*)d_in[1];
    const float* ew    = (const float*)d_in[2];
    const float* Wl    = (const float*)d_in[3];
    const float* bl    = (const float*)d_in[4];
    const float* Wr    = (const float*)d_in[5];
    const float* br    = (const float*)d_in[6];
    const float* We    = (const float*)d_in[7];
    const float* att   = (const float*)d_in[8];
    const float* cb    = (const float*)d_in[9];
    const float* gamma = (const float*)d_in[10];
    const float* beta  = (const float*)d_in[11];
    const float* W1    = (const float*)d_in[12];
    const float* b1    = (const float*)d_in[13];
    const float* W2    = (const float*)d_in[14];
    const float* b2    = (const float*)d_in[15];
    float* out = (float*)d_out;

    const int SMEM_BYTES = 2 * (BM * SAP + BK * SBP) * (int)sizeof(__half);
    cudaFuncSetAttribute(k_gemm1, cudaFuncAttributeMaxDynamicSharedMemorySize, SMEM_BYTES);

    k_init<<<4096, 256>>>();                                          // 0
    {   // xl/xr                                                        1
        long total = (long)LNUM * NN * HC;
        k_xlxr<<<(int)((total + 255) / 256), 256>>>(x, Wl, bl, Wr, br);
    }
    {   // degrees                                                      2
        long total = (long)LNUM * EE;
        k_deg<<<(int)((total + 255) / 256), 256>>>(ei, ew);
    }
    {   // fused edge pass (inline self-loop attr)                      3 (ncu target)
        dim3 grid(EGX, LNUM);
        k_edge<<<grid, 256>>>(ei, ew, We, att);
    }
    {   // node pass                                                    4
        dim3 grid(LNUM, 10);
        dim3 block(32, 8);
        k_node<<<grid, block>>>(cb);
    }
    {   // W1 -> fp16                                                   5
        long total = (long)F1 * NPAD;
        k_cvtW1<<<(int)((total + 255) / 256), 256>>>(W1);
    }
    {   // BN scale/shift                                               6
        k_bnstat<<<(F1 + 255) / 256, 256>>>(gamma, beta);
    }
    {   // BN finalize -> fp16 A operand                                7
        long total = (long)MPAD * F1;
        k_bnfin<<<(int)((total + 255) / 256), 256>>>();
    }
    {   // MLP layer 1 (fp16 tensor cores)                              8
        dim3 grid(NPAD / BN, MPAD / BM);
        k_gemm1<<<grid, 256, SMEM_BYTES>>>(b1);
    }
    {   // MLP layer 2                                                  9
        long threads = (long)NN * 32;
        k_gemm2<<<(int)((threads + 255) / 256), 256>>>(W2, b2, out);
    }
    (void)in_sizes; (void)n_in; (void)out_size;
}

// round 14
// speedup vs baseline: 2.0903x; 1.0845x over previous
#include <cuda_runtime.h>
#include <cuda_bf16.h>
#include <cuda_fp16.h>
#include <math.h>

// Problem constants
#define LNUM 25
#define NN   20000
#define EE   100000
#define ENE  120000      // EE + NN (with self loops)
#define CC   32
#define HH   2
#define HC   64          // HH*CC
#define F1   800         // LNUM*CC
#define BNEPS 1e-5f

// GEMM1 tiling: 128x64 blocks, plain fp16 mma.sync (fp32 accum), 3-stage pipe
#define MPAD 20096       // 157 * 128
#define NPAD 832         // 13 * 64
#define BM 128
#define BN 64
#define BK 32
#define SAP 40           // A smem pitch (elems): 80B rows
#define SBP 72           // B smem pitch (elems): 144B rows
#define NKITER (F1 / BK) // 25
#define NSTAGE 3

// edge kernel grid
#define EGX 250                       // blocks per layer
#define NHW (EGX * 256 / 16)          // 4000 half-warps per layer
#define EITER (ENE / NHW)             // 30 (exact)

// ---------------- scratch (device globals; no allocation allowed) -------------
__device__ float  g_xl[LNUM * NN * HC];
__device__ float  g_xr[LNUM * NN * HC];
__device__ float  g_degw[LNUM * NN * 2];     // (cnt, wsum) interleaved
__device__ float  g_denom[LNUM * NN * 2];
__device__ float  g_num[LNUM * NN * HC];
__device__ double g_bnsum[LNUM * CC];
__device__ double g_bnsq[LNUM * CC];
__device__ float  g_bnscale[F1];
__device__ float  g_bnshift[F1];
__device__ float  g_h[NN * F1];              // concat features pre-BN
__device__ __half g_hid[(size_t)NN * F1];    // MLP hidden (fp16)
__device__ __half g_Ah[(size_t)MPAD * F1];
__device__ __half g_Bh[(size_t)F1 * NPAD];

// ---------------- helpers -----------------------------------------------------
__device__ __forceinline__ void redAddV4(float* p, float a, float b, float c, float d) {
    asm volatile("red.global.add.v4.f32 [%0], {%1,%2,%3,%4};"
                 :: "l"(p), "f"(a), "f"(b), "f"(c), "f"(d) : "memory");
}
__device__ __forceinline__ void redAddV2(float* p, float a, float b) {
    asm volatile("red.global.add.v2.f32 [%0], {%1,%2};"
                 :: "l"(p), "f"(a), "f"(b) : "memory");
}
__device__ __forceinline__ unsigned su32(const void* p) {
    return (unsigned)__cvta_generic_to_shared(p);
}
__device__ __forceinline__ void cp16(unsigned s, const void* g) {
    asm volatile("cp.async.cg.shared.global [%0], [%1], 16;" :: "r"(s), "l"(g));
}
__device__ __forceinline__ void cp_commit() { asm volatile("cp.async.commit_group;"); }
template<int N> __device__ __forceinline__ void cp_wait() {
    asm volatile("cp.async.wait_group %0;" :: "n"(N));
}
__device__ __forceinline__ void ldsm_x4(unsigned* r, unsigned addr) {
    asm volatile("ldmatrix.sync.aligned.m8n8.x4.shared.b16 {%0,%1,%2,%3}, [%4];"
                 : "=r"(r[0]), "=r"(r[1]), "=r"(r[2]), "=r"(r[3]) : "r"(addr));
}
__device__ __forceinline__ void ldsm_x4_t(unsigned* r, unsigned addr) {
    asm volatile("ldmatrix.sync.aligned.m8n8.x4.trans.shared.b16 {%0,%1,%2,%3}, [%4];"
                 : "=r"(r[0]), "=r"(r[1]), "=r"(r[2]), "=r"(r[3]) : "r"(addr));
}
__device__ __forceinline__ void mma_f16(float* d, const unsigned* a, const unsigned* b) {
    asm volatile("mma.sync.aligned.m16n8k16.row.col.f32.f16.f16.f32 "
                 "{%0,%1,%2,%3}, {%4,%5,%6,%7}, {%8,%9}, {%0,%1,%2,%3};"
                 : "+f"(d[0]), "+f"(d[1]), "+f"(d[2]), "+f"(d[3])
                 : "r"(a[0]), "r"(a[1]), "r"(a[2]), "r"(a[3]), "r"(b[0]), "r"(b[1]));
}

// ---------------- kernels ------------------------------------------------------

__global__ void k_init() {
    long i0 = (long)blockIdx.x * blockDim.x + threadIdx.x;
    long st = (long)gridDim.x * blockDim.x;
    float4 z4 = make_float4(0.f, 0.f, 0.f, 0.f);
    float4* num4 = (float4*)g_num;
    for (long t = i0; t < (long)LNUM * NN * HC / 4; t += st) num4[t] = z4;
    float4* den4 = (float4*)g_denom;
    float4* dg4  = (float4*)g_degw;
    for (long t = i0; t < (long)LNUM * NN * 2 / 4; t += st) { den4[t] = z4; dg4[t] = z4; }
    for (long t = i0; t < (long)LNUM * CC; t += st) { g_bnsum[t] = 0.0; g_bnsq[t] = 0.0; }
}

// xl = x@Wl + bl ; xr = x@Wr + br.  One thread per (l, n, 4 features).
__global__ void k_xlxr(const float* __restrict__ x,
                       const float* __restrict__ Wl, const float* __restrict__ bl,
                       const float* __restrict__ Wr, const float* __restrict__ br) {
    long idx = (long)blockIdx.x * blockDim.x + threadIdx.x;
    if (idx >= (long)LNUM * NN * (HC / 4)) return;
    int j = (int)(idx % (HC / 4)) * 4;
    long r = idx / (HC / 4);
    int n = (int)(r % NN);
    int l = (int)(r / NN);
    const float* xv = x + (long)n * 5;
    float4 accl = *(const float4*)&bl[l * HC + j];
    float4 accr = *(const float4*)&br[l * HC + j];
#pragma unroll
    for (int k = 0; k < 5; k++) {
        float xk = xv[k];
        float4 wl4 = *(const float4*)&Wl[((long)l * 5 + k) * HC + j];
        float4 wr4 = *(const float4*)&Wr[((long)l * 5 + k) * HC + j];
        accl.x += xk * wl4.x; accl.y += xk * wl4.y;
        accl.z += xk * wl4.z; accl.w += xk * wl4.w;
        accr.x += xk * wr4.x; accr.y += xk * wr4.y;
        accr.z += xk * wr4.z; accr.w += xk * wr4.w;
    }
    long o = ((long)l * NN + n) * HC + j;
    *(float4*)&g_xl[o] = accl;
    *(float4*)&g_xr[o] = accr;
}

// in-degree + sum of incoming weights via one v2 reduction per edge
__global__ void k_deg(const int* __restrict__ ei, const float* __restrict__ ew) {
    long idx = (long)blockIdx.x * blockDim.x + threadIdx.x;
    if (idx >= (long)LNUM * EE) return;
    int e = (int)(idx % EE);
    int l = (int)(idx / EE);
    int d = __ldg(&ei[((long)l * 2 + 1) * EE + e]);
    redAddV2(&g_degw[((long)l * NN + d) * 2], 1.0f, __ldg(&ew[(long)l * EE + e]));
}

// FUSED edge pass.  2D grid: blockIdx.y = layer.  Each half-warp handles
// EITER=30 edges with stride NHW (exact => uniform control flow; iters 25-29
// are uniformly self loops with attr = wsum/max(cnt,1) from g_degw).
__global__ void __launch_bounds__(256) k_edge(const int* __restrict__ ei,
                                              const float* __restrict__ ew,
                                              const float* __restrict__ We,
                                              const float* __restrict__ att) {
    const int l = blockIdx.y;
    const int lane = threadIdx.x & 31;
    const int sub = lane & 15;
    const int j = sub * 4;
    const int hw0 = (blockIdx.x * 256 + threadIdx.x) >> 4;

    const float4 we4 = *(const float4*)&We[l * HC + j];
    const float4 at4 = *(const float4*)&att[l * HC + j];
    const int*   srcp = ei + (long)l * 2 * EE;
    const int*   dstp = srcp + EE;
    const float* ewp  = ew + (long)l * EE;
    const float* xlL  = g_xl + (long)l * NN * HC;
    const float* xrL  = g_xr + (long)l * NN * HC;
    const float* degwL = g_degw + (long)l * NN * 2;
    float* denomL = g_denom + (long)l * NN * 2;
    float* numL   = g_num + (long)l * NN * HC;

#pragma unroll 2
    for (int it = 0; it < EITER; it++) {
        int e = hw0 + it * NHW;
        int s, d; float w;
        if (e < EE) {
            s = __ldg(srcp + e);
            d = __ldg(dstp + e);
            w = __ldg(ewp + e);
        } else {
            s = e - EE; d = s;
            float2 dw = *(const float2*)&degwL[(long)s * 2];
            w = dw.y / fmaxf(dw.x, 1.0f);
        }
        const float4 xl4 = *(const float4*)&xlL[(long)s * HC + j];
        const float4 xr4 = *(const float4*)&xrL[(long)d * HC + j];
        float t0 = xl4.x + xr4.x + w * we4.x;
        float t1 = xl4.y + xr4.y + w * we4.y;
        float t2 = xl4.z + xr4.z + w * we4.z;
        float t3 = xl4.w + xr4.w + w * we4.w;
        t0 = t0 > 0.f ? t0 : 0.2f * t0;
        t1 = t1 > 0.f ? t1 : 0.2f * t1;
        t2 = t2 > 0.f ? t2 : 0.2f * t2;
        t3 = t3 > 0.f ? t3 : 0.2f * t3;
        float v = t0 * at4.x + t1 * at4.y + t2 * at4.z + t3 * at4.w;
        v += __shfl_xor_sync(0xffffffffu, v, 1);
        v += __shfl_xor_sync(0xffffffffu, v, 2);
        v += __shfl_xor_sync(0xffffffffu, v, 4);
        float vother = __shfl_sync(0xffffffffu, v, (lane & 16) | 8);
        float p  = __expf(v);
        float p1 = __expf(vother);
        if (sub == 0) {
            redAddV2(&denomL[(long)d * 2], p, p1);
        }
        redAddV4(&numL[(long)d * HC + j],
                 xl4.x * p, xl4.y * p, xl4.z * p, xl4.w * p);
    }
}

// Node pass: normalize, head-mean, conv bias, concat layout write, BN partials.
__global__ void k_node(const float* __restrict__ conv_bias) {
    int l = blockIdx.x;
    int c = threadIdx.x;
    int ty = threadIdx.y;
    int base = blockIdx.y * 2000;
    float cb = conv_bias[l * CC + c];
    float s1 = 0.f, s2 = 0.f;
    for (int n = base + ty; n < base + 2000; n += 8) {
        float2 den = *(const float2*)&g_denom[((long)l * NN + n) * 2];
        float deg  = g_degw[((long)l * NN + n) * 2] + 1.0f;
        long nb = ((long)l * NN + n) * HC;
        float o = 0.5f * (g_num[nb + c] / den.x + g_num[nb + 32 + c] / den.y) / deg + cb;
        g_h[(long)n * F1 + l * CC + c] = o;
        s1 += o;
        s2 += o * o;
    }
    __shared__ float sm1[8][32];
    __shared__ float sm2[8][32];
    sm1[ty][c] = s1; sm2[ty][c] = s2;
    __syncthreads();
    if (ty == 0) {
        float t1 = 0.f, t2 = 0.f;
#pragma unroll
        for (int y = 0; y < 8; y++) { t1 += sm1[y][c]; t2 += sm2[y][c]; }
        atomicAdd(&g_bnsum[l * CC + c], (double)t1);
        atomicAdd(&g_bnsq[l * CC + c], (double)t2);
    }
}

// Tiny: turn BN sums into per-feature scale/shift
__global__ void k_bnstat(const float* __restrict__ gamma1, const float* __restrict__ beta1) {
    int f = blockIdx.x * blockDim.x + threadIdx.x;
    if (f >= F1) return;
    double mean = g_bnsum[f] * (1.0 / NN);
    double var  = g_bnsq[f] * (1.0 / NN) - mean * mean;
    float inv = rsqrtf((float)var + BNEPS);
    float sc = gamma1[f] * inv;
    g_bnscale[f] = sc;
    g_bnshift[f] = beta1[f] - sc * (float)mean;
}

// BN finalize + leaky(0.01) -> fp16 GEMM A operand.  4 features per thread.
__global__ void k_bnfin() {
    long idx = (long)blockIdx.x * blockDim.x + threadIdx.x;
    if (idx >= (long)MPAD * (F1 / 4)) return;
    int f = (int)(idx % (F1 / 4)) * 4;
    long row = idx / (F1 / 4);
    __half2 h0, h1;
    if (row < NN) {
        float4 h4 = *(const float4*)&g_h[row * F1 + f];
        float4 sc = *(const float4*)&g_bnscale[f];
        float4 sh = *(const float4*)&g_bnshift[f];
        float o0 = sc.x * h4.x + sh.x;
        float o1 = sc.y * h4.y + sh.y;
        float o2 = sc.z * h4.z + sh.z;
        float o3 = sc.w * h4.w + sh.w;
        o0 = o0 > 0.f ? o0 : 0.01f * o0;
        o1 = o1 > 0.f ? o1 : 0.01f * o1;
        o2 = o2 > 0.f ? o2 : 0.01f * o2;
        o3 = o3 > 0.f ? o3 : 0.01f * o3;
        h0 = __floats2half2_rn(o0, o1);
        h1 = __floats2half2_rn(o2, o3);
    } else {
        h0 = __floats2half2_rn(0.f, 0.f);
        h1 = h0;
    }
    __half2* dst = (__half2*)&g_Ah[row * F1 + f];
    dst[0] = h0;
    dst[1] = h1;
}

// W1 -> fp16 (round-to-nearest), N padded to 832
__global__ void k_cvtW1(const float* __restrict__ W1) {
    long idx = (long)blockIdx.x * blockDim.x + threadIdx.x;
    if (idx >= (long)F1 * NPAD) return;
    int n = (int)(idx % NPAD);
    int k = (int)(idx / NPAD);
    float v = (n < F1) ? W1[(long)k * F1 + n] : 0.f;
    g_Bh[idx] = __float2half_rn(v);
}

// GEMM1: g_hid = relu(A[20000,800] @ W1[800,800] + b1), plain fp16 mma.sync,
// fp32 accum, fp16 output.  128x64 tile, 8 warps of 32x32, 3-stage pipeline.
__global__ void __launch_bounds__(256, 3) k_gemm1(const float* __restrict__ bias) {
    extern __shared__ __half sm[];
    const int tid = threadIdx.x;
    const int wid = tid >> 5, lane = tid & 31;
    const int wm = wid >> 1, wn = wid & 1;      // 4 x 2 warp grid, 32x32 per warp
    const int rowBase = blockIdx.y * BM, nBase = blockIdx.x * BN;

    const int AOFF = BM * SAP;                  // 5120 elems
    const int BOFF = BK * SBP;                  // 2304 elems
    const int STAGE_E = AOFF + BOFF;            // 7424 elems (14.5 KB)

    float acc[2][4][4];
#pragma unroll
    for (int i = 0; i < 2; i++)
#pragma unroll
        for (int j = 0; j < 4; j++)
#pragma unroll
            for (int k = 0; k < 4; k++) acc[i][j][k] = 0.f;

    auto load_stage = [&](int ks, int buf) {
        const int k0 = ks * BK;
        __half* base = sm + buf * STAGE_E;
#pragma unroll
        for (int i = 0; i < 2; i++) {
            int c = tid + i * 256;
            int row = c >> 2, seg = c & 3;
            cp16(su32(base + row * SAP + seg * 8),
                 g_Ah + (size_t)(rowBase + row) * F1 + k0 + seg * 8);
        }
        {
            int kr = tid >> 3, seg = tid & 7;
            cp16(su32(base + AOFF + kr * SBP + seg * 8),
                 g_Bh + (size_t)(k0 + kr) * NPAD + nBase + seg * 8);
        }
        cp_commit();
    };

    const int grp = lane >> 3, lr = lane & 7;

    auto compute_stage = [&](int buf) {
        __half* base = sm + buf * STAGE_E;
#pragma unroll
        for (int kk = 0; kk < 2; kk++) {
            unsigned af[2][4], bf[2][4];
            int acol = kk * 16 + (grp >> 1) * 8;
#pragma unroll
            for (int mt = 0; mt < 2; mt++) {
                int arow = wm * 32 + mt * 16 + (grp & 1) * 8 + lr;
                ldsm_x4(af[mt], su32(base + arow * SAP + acol));
            }
            int krow = kk * 16 + (grp & 1) * 8 + lr;
#pragma unroll
            for (int np = 0; np < 2; np++) {
                int ncol = wn * 32 + np * 16 + (grp >> 1) * 8;
                ldsm_x4_t(bf[np], su32(base + AOFF + krow * SBP + ncol));
            }
#pragma unroll
            for (int mt = 0; mt < 2; mt++)
#pragma unroll
                for (int nt = 0; nt < 4; nt++) {
                    const unsigned* b = &bf[nt >> 1][(nt & 1) * 2];
                    mma_f16(acc[mt][nt], af[mt], b);
                }
        }
    };

    load_stage(0, 0);
    load_stage(1, 1);
    for (int ks = 0; ks < NKITER; ks++) {
        if (ks + 2 < NKITER) {
            load_stage(ks + 2, (ks + 2) % NSTAGE);
            cp_wait<2>();
        } else if (ks + 1 < NKITER) {
            cp_wait<1>();
        } else {
            cp_wait<0>();
        }
        __syncthreads();
        compute_stage(ks % NSTAGE);
        __syncthreads();
    }

#pragma unroll
    for (int mt = 0; mt < 2; mt++) {
#pragma unroll
        for (int nt = 0; nt < 4; nt++) {
            int row0 = rowBase + wm * 32 + mt * 16 + (lane >> 2);
            int col0 = nBase + wn * 32 + nt * 8 + (lane & 3) * 2;
            float* a = acc[mt][nt];
            if (col0 < F1) {    // col0 even, F1 even => col0+1 < F1 too
                float b0 = bias[col0], b1 = bias[col0 + 1];
                if (row0 < NN) {
                    float v0 = fmaxf(a[0] + b0, 0.f);
                    float v1 = fmaxf(a[1] + b1, 0.f);
                    *(__half2*)&g_hid[(size_t)row0 * F1 + col0] = __floats2half2_rn(v0, v1);
                }
                if (row0 + 8 < NN) {
                    float v2 = fmaxf(a[2] + b0, 0.f);
                    float v3 = fmaxf(a[3] + b1, 0.f);
                    *(__half2*)&g_hid[(size_t)(row0 + 8) * F1 + col0] = __floats2half2_rn(v2, v3);
                }
            }
        }
    }
}

// out = g_hid[20000,800](fp16) @ W2[800,5] + b2. One warp per row.
__global__ void k_gemm2(const float* __restrict__ W2, const float* __restrict__ b2,
                        float* __restrict__ out) {
    long w = ((long)blockIdx.x * blockDim.x + threadIdx.x) >> 5;
    int lane = threadIdx.x & 31;
    if (w >= NN) return;
    const __half* hr = g_hid + (size_t)w * F1;
    float a0 = 0.f, a1 = 0.f, a2 = 0.f, a3 = 0.f, a4 = 0.f;
    for (int k4 = lane * 4; k4 < F1; k4 += 128) {
        uint2 u = *(const uint2*)(hr + k4);
        float2 f01 = __half22float2(*(const __half2*)&u.x);
        float2 f23 = __half22float2(*(const __half2*)&u.y);
        float hs[4] = {f01.x, f01.y, f23.x, f23.y};
#pragma unroll
        for (int t = 0; t < 4; t++) {
            const float* wv = W2 + (k4 + t) * 5;
            float hk = hs[t];
            a0 += hk * wv[0];
            a1 += hk * wv[1];
            a2 += hk * wv[2];
            a3 += hk * wv[3];
            a4 += hk * wv[4];
        }
    }
#pragma unroll
    for (int o = 16; o; o >>= 1) {
        a0 += __shfl_xor_sync(0xffffffffu, a0, o);
        a1 += __shfl_xor_sync(0xffffffffu, a1, o);
        a2 += __shfl_xor_sync(0xffffffffu, a2, o);
        a3 += __shfl_xor_sync(0xffffffffu, a3, o);
        a4 += __shfl_xor_sync(0xffffffffu, a4, o);
    }
    if (lane == 0) {
        out[w * 5 + 0] = a0 + b2[0];
        out[w * 5 + 1] = a1 + b2[1];
        out[w * 5 + 2] = a2 + b2[2];
        out[w * 5 + 3] = a3 + b2[3];
        out[w * 5 + 4] = a4 + b2[4];
    }
}

// ---------------- launcher ----------------------------------------------------
extern "C" void kernel_launch(void* const* d_in, const int* in_sizes, int n_in,
                              void* d_out, int out_size) {
    const float* x     = (const float*)d_in[0];
    const int*   ei    = (const int*)d_in[1];
    const float* ew    = (const float*)d_in[2];
    const float* Wl    = (const float*)d_in[3];
    const float* bl    = (const float*)d_in[4];
    const float* Wr    = (const float*)d_in[5];
    const float* br    = (const float*)d_in[6];
    const float* We    = (const float*)d_in[7];
    const float* att   = (const float*)d_in[8];
    const float* cb    = (const float*)d_in[9];
    const float* gamma = (const float*)d_in[10];
    const float* beta  = (const float*)d_in[11];
    const float* W1    = (const float*)d_in[12];
    const float* b1    = (const float*)d_in[13];
    const float* W2    = (const float*)d_in[14];
    const float* b2    = (const float*)d_in[15];
    float* out = (float*)d_out;

    const int SMEM_BYTES = NSTAGE * (BM * SAP + BK * SBP) * (int)sizeof(__half);
    cudaFuncSetAttribute(k_gemm1, cudaFuncAttributeMaxDynamicSharedMemorySize, SMEM_BYTES);

    k_init<<<2048, 256>>>();                                          // 0
    {   // xl/xr (vectorized x4)                                        1
        long total = (long)LNUM * NN * (HC / 4);
        k_xlxr<<<(int)((total + 255) / 256), 256>>>(x, Wl, bl, Wr, br);
    }
    {   // degrees                                                      2
        long total = (long)LNUM * EE;
        k_deg<<<(int)((total + 255) / 256), 256>>>(ei, ew);
    }
    {   // fused edge pass (inline self-loop attr)                      3 (ncu target)
        dim3 grid(EGX, LNUM);
        k_edge<<<grid, 256>>>(ei, ew, We, att);
    }
    {   // node pass                                                    4
        dim3 grid(LNUM, 10);
        dim3 block(32, 8);
        k_node<<<grid, block>>>(cb);
    }
    {   // W1 -> fp16                                                   5
        long total = (long)F1 * NPAD;
        k_cvtW1<<<(int)((total + 255) / 256), 256>>>(W1);
    }
    {   // BN scale/shift                                               6
        k_bnstat<<<(F1 + 255) / 256, 256>>>(gamma, beta);
    }
    {   // BN finalize -> fp16 A operand (vectorized x4)                7
        long total = (long)MPAD * (F1 / 4);
        k_bnfin<<<(int)((total + 255) / 256), 256>>>();
    }
    {   // MLP layer 1 (fp16 tensor cores, 3-stage)                     8
        dim3 grid(NPAD / BN, MPAD / BM);
        k_gemm1<<<grid, 256, SMEM_BYTES>>>(b1);
    }
    {   // MLP layer 2 (fp16 input)                                     9
        long threads = (long)NN * 32;
        k_gemm2<<<(int)((threads + 255) / 256), 256>>>(W2, b2, out);
    }
    (void)in_sizes; (void)n_in; (void)out_size;
}

// round 15
// speedup vs baseline: 2.1246x; 1.0164x over previous
#include <cuda_runtime.h>
#include <cuda_bf16.h>
#include <cuda_fp16.h>
#include <math.h>

// Problem constants
#define LNUM 25
#define NN   20000
#define EE   100000
#define ENE  120000      // EE + NN (with self loops)
#define CC   32
#define HH   2
#define HC   64          // HH*CC
#define F1   800         // LNUM*CC
#define BNEPS 1e-5f

// GEMM1 tiling: 128x128 blocks, plain fp16 mma.sync (fp32 accum), 3-stage pipe
#define MPAD 20096       // 157 * 128
#define NPAD 896         // 7 * 128
#define BM 128
#define BN 128
#define BK 32
#define SAP 40           // A smem pitch (elems): 80B rows
#define SBP 136          // B smem pitch (elems): 272B rows
#define NKITER (F1 / BK) // 25
#define NSTAGE 3

// edge kernel grid
#define EGX 250                       // blocks per layer
#define NHW (EGX * 256 / 16)          // 4000 half-warps per layer
#define EITER (ENE / NHW)             // 30 (exact)

// ---------------- scratch (device globals; no allocation allowed) -------------
__device__ float  g_xl[LNUM * NN * HC];
__device__ float  g_xr[LNUM * NN * HC];
__device__ float  g_degw[LNUM * NN * 2];     // (cnt, wsum) interleaved
__device__ float  g_denom[LNUM * NN * 2];
__device__ float  g_num[LNUM * NN * HC];
__device__ double g_bnsum[LNUM * CC];
__device__ double g_bnsq[LNUM * CC];
__device__ float  g_bnscale[F1];
__device__ float  g_bnshift[F1];
__device__ __half g_h[(size_t)NN * F1];      // concat features pre-BN (fp16)
__device__ __half g_hid[(size_t)NN * F1];    // MLP hidden (fp16)
__device__ __half g_Ah[(size_t)MPAD * F1];
__device__ __half g_Bh[(size_t)F1 * NPAD];

// ---------------- helpers -----------------------------------------------------
__device__ __forceinline__ void redAddV4(float* p, float a, float b, float c, float d) {
    asm volatile("red.global.add.v4.f32 [%0], {%1,%2,%3,%4};"
                 :: "l"(p), "f"(a), "f"(b), "f"(c), "f"(d) : "memory");
}
__device__ __forceinline__ void redAddV2(float* p, float a, float b) {
    asm volatile("red.global.add.v2.f32 [%0], {%1,%2};"
                 :: "l"(p), "f"(a), "f"(b) : "memory");
}
__device__ __forceinline__ unsigned su32(const void* p) {
    return (unsigned)__cvta_generic_to_shared(p);
}
__device__ __forceinline__ void cp16(unsigned s, const void* g) {
    asm volatile("cp.async.cg.shared.global [%0], [%1], 16;" :: "r"(s), "l"(g));
}
__device__ __forceinline__ void cp_commit() { asm volatile("cp.async.commit_group;"); }
template<int N> __device__ __forceinline__ void cp_wait() {
    asm volatile("cp.async.wait_group %0;" :: "n"(N));
}
__device__ __forceinline__ void ldsm_x4(unsigned* r, unsigned addr) {
    asm volatile("ldmatrix.sync.aligned.m8n8.x4.shared.b16 {%0,%1,%2,%3}, [%4];"
                 : "=r"(r[0]), "=r"(r[1]), "=r"(r[2]), "=r"(r[3]) : "r"(addr));
}
__device__ __forceinline__ void ldsm_x4_t(unsigned* r, unsigned addr) {
    asm volatile("ldmatrix.sync.aligned.m8n8.x4.trans.shared.b16 {%0,%1,%2,%3}, [%4];"
                 : "=r"(r[0]), "=r"(r[1]), "=r"(r[2]), "=r"(r[3]) : "r"(addr));
}
__device__ __forceinline__ void mma_f16(float* d, const unsigned* a, const unsigned* b) {
    asm volatile("mma.sync.aligned.m16n8k16.row.col.f32.f16.f16.f32 "
                 "{%0,%1,%2,%3}, {%4,%5,%6,%7}, {%8,%9}, {%0,%1,%2,%3};"
                 : "+f"(d[0]), "+f"(d[1]), "+f"(d[2]), "+f"(d[3])
                 : "r"(a[0]), "r"(a[1]), "r"(a[2]), "r"(a[3]), "r"(b[0]), "r"(b[1]));
}

// ---------------- kernels ------------------------------------------------------

__global__ void k_init() {
    long i0 = (long)blockIdx.x * blockDim.x + threadIdx.x;
    long st = (long)gridDim.x * blockDim.x;
    float4 z4 = make_float4(0.f, 0.f, 0.f, 0.f);
    float4* num4 = (float4*)g_num;
    for (long t = i0; t < (long)LNUM * NN * HC / 4; t += st) num4[t] = z4;
    float4* den4 = (float4*)g_denom;
    float4* dg4  = (float4*)g_degw;
    for (long t = i0; t < (long)LNUM * NN * 2 / 4; t += st) { den4[t] = z4; dg4[t] = z4; }
    for (long t = i0; t < (long)LNUM * CC; t += st) { g_bnsum[t] = 0.0; g_bnsq[t] = 0.0; }
}

// xl = x@Wl + bl ; xr = x@Wr + br.  One thread per (l, n, 4 features).
__global__ void k_xlxr(const float* __restrict__ x,
                       const float* __restrict__ Wl, const float* __restrict__ bl,
                       const float* __restrict__ Wr, const float* __restrict__ br) {
    long idx = (long)blockIdx.x * blockDim.x + threadIdx.x;
    if (idx >= (long)LNUM * NN * (HC / 4)) return;
    int j = (int)(idx % (HC / 4)) * 4;
    long r = idx / (HC / 4);
    int n = (int)(r % NN);
    int l = (int)(r / NN);
    const float* xv = x + (long)n * 5;
    float4 accl = *(const float4*)&bl[l * HC + j];
    float4 accr = *(const float4*)&br[l * HC + j];
#pragma unroll
    for (int k = 0; k < 5; k++) {
        float xk = xv[k];
        float4 wl4 = *(const float4*)&Wl[((long)l * 5 + k) * HC + j];
        float4 wr4 = *(const float4*)&Wr[((long)l * 5 + k) * HC + j];
        accl.x += xk * wl4.x; accl.y += xk * wl4.y;
        accl.z += xk * wl4.z; accl.w += xk * wl4.w;
        accr.x += xk * wr4.x; accr.y += xk * wr4.y;
        accr.z += xk * wr4.z; accr.w += xk * wr4.w;
    }
    long o = ((long)l * NN + n) * HC + j;
    *(float4*)&g_xl[o] = accl;
    *(float4*)&g_xr[o] = accr;
}

// in-degree + wsum; 2 edges per thread (vectorized index/weight loads)
__global__ void k_deg(const int* __restrict__ ei, const float* __restrict__ ew) {
    long idx = (long)blockIdx.x * blockDim.x + threadIdx.x;
    if (idx >= (long)LNUM * (EE / 2)) return;
    int e2 = (int)(idx % (EE / 2)) * 2;
    int l = (int)(idx / (EE / 2));
    int2   d2 = *(const int2*)&ei[((long)l * 2 + 1) * EE + e2];
    float2 w2 = *(const float2*)&ew[(long)l * EE + e2];
    float* degwL = g_degw + (long)l * NN * 2;
    redAddV2(&degwL[(long)d2.x * 2], 1.0f, w2.x);
    redAddV2(&degwL[(long)d2.y * 2], 1.0f, w2.y);
}

// FUSED edge pass.  2D grid: blockIdx.y = layer.  Each half-warp handles
// EITER=30 edges with stride NHW (exact => uniform control flow; iters 25-29
// are uniformly self loops with attr = wsum/max(cnt,1) from g_degw).
__global__ void __launch_bounds__(256) k_edge(const int* __restrict__ ei,
                                              const float* __restrict__ ew,
                                              const float* __restrict__ We,
                                              const float* __restrict__ att) {
    const int l = blockIdx.y;
    const int lane = threadIdx.x & 31;
    const int sub = lane & 15;
    const int j = sub * 4;
    const int hw0 = (blockIdx.x * 256 + threadIdx.x) >> 4;

    const float4 we4 = *(const float4*)&We[l * HC + j];
    const float4 at4 = *(const float4*)&att[l * HC + j];
    const int*   srcp = ei + (long)l * 2 * EE;
    const int*   dstp = srcp + EE;
    const float* ewp  = ew + (long)l * EE;
    const float* xlL  = g_xl + (long)l * NN * HC;
    const float* xrL  = g_xr + (long)l * NN * HC;
    const float* degwL = g_degw + (long)l * NN * 2;
    float* denomL = g_denom + (long)l * NN * 2;
    float* numL   = g_num + (long)l * NN * HC;

#pragma unroll 2
    for (int it = 0; it < EITER; it++) {
        int e = hw0 + it * NHW;
        int s, d; float w;
        if (e < EE) {
            s = __ldg(srcp + e);
            d = __ldg(dstp + e);
            w = __ldg(ewp + e);
        } else {
            s = e - EE; d = s;
            float2 dw = *(const float2*)&degwL[(long)s * 2];
            w = dw.y / fmaxf(dw.x, 1.0f);
        }
        const float4 xl4 = *(const float4*)&xlL[(long)s * HC + j];
        const float4 xr4 = *(const float4*)&xrL[(long)d * HC + j];
        float t0 = xl4.x + xr4.x + w * we4.x;
        float t1 = xl4.y + xr4.y + w * we4.y;
        float t2 = xl4.z + xr4.z + w * we4.z;
        float t3 = xl4.w + xr4.w + w * we4.w;
        t0 = t0 > 0.f ? t0 : 0.2f * t0;
        t1 = t1 > 0.f ? t1 : 0.2f * t1;
        t2 = t2 > 0.f ? t2 : 0.2f * t2;
        t3 = t3 > 0.f ? t3 : 0.2f * t3;
        float v = t0 * at4.x + t1 * at4.y + t2 * at4.z + t3 * at4.w;
        v += __shfl_xor_sync(0xffffffffu, v, 1);
        v += __shfl_xor_sync(0xffffffffu, v, 2);
        v += __shfl_xor_sync(0xffffffffu, v, 4);
        float vother = __shfl_sync(0xffffffffu, v, (lane & 16) | 8);
        float p  = __expf(v);
        float p1 = __expf(vother);
        if (sub == 0) {
            redAddV2(&denomL[(long)d * 2], p, p1);
        }
        redAddV4(&numL[(long)d * HC + j],
                 xl4.x * p, xl4.y * p, xl4.z * p, xl4.w * p);
    }
}

// Node pass: normalize, head-mean, conv bias, concat write (fp16), BN partials.
__global__ void k_node(const float* __restrict__ conv_bias) {
    int l = blockIdx.x;
    int c = threadIdx.x;
    int ty = threadIdx.y;
    int base = blockIdx.y * 2000;
    float cb = conv_bias[l * CC + c];
    float s1 = 0.f, s2 = 0.f;
    for (int n = base + ty; n < base + 2000; n += 8) {
        float2 den = *(const float2*)&g_denom[((long)l * NN + n) * 2];
        float deg  = g_degw[((long)l * NN + n) * 2] + 1.0f;
        long nb = ((long)l * NN + n) * HC;
        float o = 0.5f * (g_num[nb + c] / den.x + g_num[nb + 32 + c] / den.y) / deg + cb;
        g_h[(size_t)n * F1 + l * CC + c] = __float2half_rn(o);
        s1 += o;
        s2 += o * o;
    }
    __shared__ float sm1[8][32];
    __shared__ float sm2[8][32];
    sm1[ty][c] = s1; sm2[ty][c] = s2;
    __syncthreads();
    if (ty == 0) {
        float t1 = 0.f, t2 = 0.f;
#pragma unroll
        for (int y = 0; y < 8; y++) { t1 += sm1[y][c]; t2 += sm2[y][c]; }
        atomicAdd(&g_bnsum[l * CC + c], (double)t1);
        atomicAdd(&g_bnsq[l * CC + c], (double)t2);
    }
}

// Tiny: turn BN sums into per-feature scale/shift
__global__ void k_bnstat(const float* __restrict__ gamma1, const float* __restrict__ beta1) {
    int f = blockIdx.x * blockDim.x + threadIdx.x;
    if (f >= F1) return;
    double mean = g_bnsum[f] * (1.0 / NN);
    double var  = g_bnsq[f] * (1.0 / NN) - mean * mean;
    float inv = rsqrtf((float)var + BNEPS);
    float sc = gamma1[f] * inv;
    g_bnscale[f] = sc;
    g_bnshift[f] = beta1[f] - sc * (float)mean;
}

// BN finalize + leaky(0.01) -> fp16 GEMM A operand.  4 features per thread.
__global__ void k_bnfin() {
    long idx = (long)blockIdx.x * blockDim.x + threadIdx.x;
    if (idx >= (long)MPAD * (F1 / 4)) return;
    int f = (int)(idx % (F1 / 4)) * 4;
    long row = idx / (F1 / 4);
    __half2 h0, h1;
    if (row < NN) {
        uint2 u = *(const uint2*)&g_h[row * F1 + f];
        float2 f01 = __half22float2(*(const __half2*)&u.x);
        float2 f23 = __half22float2(*(const __half2*)&u.y);
        float4 sc = *(const float4*)&g_bnscale[f];
        float4 sh = *(const float4*)&g_bnshift[f];
        float o0 = sc.x * f01.x + sh.x;
        float o1 = sc.y * f01.y + sh.y;
        float o2 = sc.z * f23.x + sh.z;
        float o3 = sc.w * f23.y + sh.w;
        o0 = o0 > 0.f ? o0 : 0.01f * o0;
        o1 = o1 > 0.f ? o1 : 0.01f * o1;
        o2 = o2 > 0.f ? o2 : 0.01f * o2;
        o3 = o3 > 0.f ? o3 : 0.01f * o3;
        h0 = __floats2half2_rn(o0, o1);
        h1 = __floats2half2_rn(o2, o3);
    } else {
        h0 = __floats2half2_rn(0.f, 0.f);
        h1 = h0;
    }
    __half2* dst = (__half2*)&g_Ah[row * F1 + f];
    dst[0] = h0;
    dst[1] = h1;
}

// W1 -> fp16 (round-to-nearest), N padded to 896
__global__ void k_cvtW1(const float* __restrict__ W1) {
    long idx = (long)blockIdx.x * blockDim.x + threadIdx.x;
    if (idx >= (long)F1 * NPAD) return;
    int n = (int)(idx % NPAD);
    int k = (int)(idx / NPAD);
    float v = (n < F1) ? W1[(long)k * F1 + n] : 0.f;
    g_Bh[idx] = __float2half_rn(v);
}

// GEMM1: g_hid = relu(A[20000,800] @ W1[800,800] + b1), plain fp16 mma.sync,
// fp32 accum, fp16 output.  128x128 tile, 8 warps of 32x64, 3-stage pipeline.
__global__ void __launch_bounds__(256, 2) k_gemm1(const float* __restrict__ bias) {
    extern __shared__ __half sm[];
    const int tid = threadIdx.x;
    const int wid = tid >> 5, lane = tid & 31;
    const int wm = wid >> 1, wn = wid & 1;      // 4 x 2 warp grid, 32x64 per warp
    const int rowBase = blockIdx.y * BM, nBase = blockIdx.x * BN;

    const int AOFF = BM * SAP;                  // 5120 elems
    const int BOFF = BK * SBP;                  // 4352 elems
    const int STAGE_E = AOFF + BOFF;            // 9472 elems (18.5 KB)

    float acc[2][8][4];
#pragma unroll
    for (int i = 0; i < 2; i++)
#pragma unroll
        for (int j = 0; j < 8; j++)
#pragma unroll
            for (int k = 0; k < 4; k++) acc[i][j][k] = 0.f;

    auto load_stage = [&](int ks, int buf) {
        const int k0 = ks * BK;
        __half* base = sm + buf * STAGE_E;
        // A: 128 rows x 32 k = 512 slots of 8 halves, 2 per thread
#pragma unroll
        for (int i = 0; i < 2; i++) {
            int c = tid + i * 256;
            int row = c >> 2, seg = c & 3;
            cp16(su32(base + row * SAP + seg * 8),
                 g_Ah + (size_t)(rowBase + row) * F1 + k0 + seg * 8);
        }
        // B: 32 k-rows x 128 cols = 512 slots of 8 halves, 2 per thread
#pragma unroll
        for (int i = 0; i < 2; i++) {
            int c = tid + i * 256;
            int kr = c >> 4, seg = c & 15;
            cp16(su32(base + AOFF + kr * SBP + seg * 8),
                 g_Bh + (size_t)(k0 + kr) * NPAD + nBase + seg * 8);
        }
        cp_commit();
    };

    const int grp = lane >> 3, lr = lane & 7;

    auto compute_stage = [&](int buf) {
        __half* base = sm + buf * STAGE_E;
#pragma unroll
        for (int kk = 0; kk < 2; kk++) {
            unsigned af[2][4], bf[4][4];
            int acol = kk * 16 + (grp >> 1) * 8;
#pragma unroll
            for (int mt = 0; mt < 2; mt++) {
                int arow = wm * 32 + mt * 16 + (grp & 1) * 8 + lr;
                ldsm_x4(af[mt], su32(base + arow * SAP + acol));
            }
            int krow = kk * 16 + (grp & 1) * 8 + lr;
#pragma unroll
            for (int np = 0; np < 4; np++) {
                int ncol = wn * 64 + np * 16 + (grp >> 1) * 8;
                ldsm_x4_t(bf[np], su32(base + AOFF + krow * SBP + ncol));
            }
#pragma unroll
            for (int mt = 0; mt < 2; mt++)
#pragma unroll
                for (int nt = 0; nt < 8; nt++) {
                    const unsigned* b = &bf[nt >> 1][(nt & 1) * 2];
                    mma_f16(acc[mt][nt], af[mt], b);
                }
        }
    };

    load_stage(0, 0);
    load_stage(1, 1);
    for (int ks = 0; ks < NKITER; ks++) {
        if (ks + 2 < NKITER) {
            load_stage(ks + 2, (ks + 2) % NSTAGE);
            cp_wait<2>();
        } else if (ks + 1 < NKITER) {
            cp_wait<1>();
        } else {
            cp_wait<0>();
        }
        __syncthreads();
        compute_stage(ks % NSTAGE);
        __syncthreads();
    }

#pragma unroll
    for (int mt = 0; mt < 2; mt++) {
#pragma unroll
        for (int nt = 0; nt < 8; nt++) {
            int row0 = rowBase + wm * 32 + mt * 16 + (lane >> 2);
            int col0 = nBase + wn * 64 + nt * 8 + (lane & 3) * 2;
            float* a = acc[mt][nt];
            if (col0 < F1) {    // col0 even, F1 even => col0+1 < F1 too
                float b0 = bias[col0], b1 = bias[col0 + 1];
                if (row0 < NN) {
                    float v0 = fmaxf(a[0] + b0, 0.f);
                    float v1 = fmaxf(a[1] + b1, 0.f);
                    *(__half2*)&g_hid[(size_t)row0 * F1 + col0] = __floats2half2_rn(v0, v1);
                }
                if (row0 + 8 < NN) {
                    float v2 = fmaxf(a[2] + b0, 0.f);
                    float v3 = fmaxf(a[3] + b1, 0.f);
                    *(__half2*)&g_hid[(size_t)(row0 + 8) * F1 + col0] = __floats2half2_rn(v2, v3);
                }
            }
        }
    }
}

// out = g_hid[20000,800](fp16) @ W2[800,5] + b2. One warp per row.
__global__ void k_gemm2(const float* __restrict__ W2, const float* __restrict__ b2,
                        float* __restrict__ out) {
    long w = ((long)blockIdx.x * blockDim.x + threadIdx.x) >> 5;
    int lane = threadIdx.x & 31;
    if (w >= NN) return;
    const __half* hr = g_hid + (size_t)w * F1;
    float a0 = 0.f, a1 = 0.f, a2 = 0.f, a3 = 0.f, a4 = 0.f;
    for (int k4 = lane * 4; k4 < F1; k4 += 128) {
        uint2 u = *(const uint2*)(hr + k4);
        float2 f01 = __half22float2(*(const __half2*)&u.x);
        float2 f23 = __half22float2(*(const __half2*)&u.y);
        float hs[4] = {f01.x, f01.y, f23.x, f23.y};
#pragma unroll
        for (int t = 0; t < 4; t++) {
            const float* wv = W2 + (k4 + t) * 5;
            float hk = hs[t];
            a0 += hk * wv[0];
            a1 += hk * wv[1];
            a2 += hk * wv[2];
            a3 += hk * wv[3];
            a4 += hk * wv[4];
        }
    }
#pragma unroll
    for (int o = 16; o; o >>= 1) {
        a0 += __shfl_xor_sync(0xffffffffu, a0, o);
        a1 += __shfl_xor_sync(0xffffffffu, a1, o);
        a2 += __shfl_xor_sync(0xffffffffu, a2, o);
        a3 += __shfl_xor_sync(0xffffffffu, a3, o);
        a4 += __shfl_xor_sync(0xffffffffu, a4, o);
    }
    if (lane == 0) {
        out[w * 5 + 0] = a0 + b2[0];
        out[w * 5 + 1] = a1 + b2[1];
        out[w * 5 + 2] = a2 + b2[2];
        out[w * 5 + 3] = a3 + b2[3];
        out[w * 5 + 4] = a4 + b2[4];
    }
}

// ---------------- launcher ----------------------------------------------------
extern "C" void kernel_launch(void* const* d_in, const int* in_sizes, int n_in,
                              void* d_out, int out_size) {
    const float* x     = (const float*)d_in[0];
    const int*   ei    = (const int*)d_in[1];
    const float* ew    = (const float*)d_in[2];
    const float* Wl    = (const float*)d_in[3];
    const float* bl    = (const float*)d_in[4];
    const float* Wr    = (const float*)d_in[5];
    const float* br    = (const float*)d_in[6];
    const float* We    = (const float*)d_in[7];
    const float* att   = (const float*)d_in[8];
    const float* cb    = (const float*)d_in[9];
    const float* gamma = (const float*)d_in[10];
    const float* beta  = (const float*)d_in[11];
    const float* W1    = (const float*)d_in[12];
    const float* b1    = (const float*)d_in[13];
    const float* W2    = (const float*)d_in[14];
    const float* b2    = (const float*)d_in[15];
    float* out = (float*)d_out;

    const int SMEM_BYTES = NSTAGE * (BM * SAP + BK * SBP) * (int)sizeof(__half);
    cudaFuncSetAttribute(k_gemm1, cudaFuncAttributeMaxDynamicSharedMemorySize, SMEM_BYTES);

    k_init<<<2048, 256>>>();                                          // 0
    {   // xl/xr (vectorized x4)                                        1
        long total = (long)LNUM * NN * (HC / 4);
        k_xlxr<<<(int)((total + 255) / 256), 256>>>(x, Wl, bl, Wr, br);
    }
    {   // degrees (2 edges / thread)                                   2
        long total = (long)LNUM * (EE / 2);
        k_deg<<<(int)((total + 255) / 256), 256>>>(ei, ew);
    }
    {   // fused edge pass (inline self-loop attr)                      3 (ncu target)
        dim3 grid(EGX, LNUM);
        k_edge<<<grid, 256>>>(ei, ew, We, att);
    }
    {   // node pass (fp16 h)                                           4
        dim3 grid(LNUM, 10);
        dim3 block(32, 8);
        k_node<<<grid, block>>>(cb);
    }
    {   // W1 -> fp16                                                   5
        long total = (long)F1 * NPAD;
        k_cvtW1<<<(int)((total + 255) / 256), 256>>>(W1);
    }
    {   // BN scale/shift                                               6
        k_bnstat<<<(F1 + 255) / 256, 256>>>(gamma, beta);
    }
    {   // BN finalize -> fp16 A operand (vectorized x4)                7
        long total = (long)MPAD * (F1 / 4);
        k_bnfin<<<(int)((total + 255) / 256), 256>>>();
    }
    {   // MLP layer 1 (fp16 tensor cores, 128x128, 3-stage)            8
        dim3 grid(NPAD / BN, MPAD / BM);
        k_gemm1<<<grid, 256, SMEM_BYTES>>>(b1);
    }
    {   // MLP layer 2 (fp16 input)                                     9
        long threads = (long)NN * 32;
        k_gemm2<<<(int)((threads + 255) / 256), 256>>>(W2, b2, out);
    }
    (void)in_sizes; (void)n_in; (void)out_size;
}

// round 16
// speedup vs baseline: 2.2054x; 1.0380x over previous
#include <cuda_runtime.h>
#include <cuda_bf16.h>
#include <cuda_fp16.h>
#include <math.h>

// Problem constants
#define LNUM 25
#define NN   20000
#define EE   100000
#define ENE  120000      // EE + NN (with self loops)
#define CC   32
#define HH   2
#define HC   64          // HH*CC
#define F1   800         // LNUM*CC
#define BNEPS 1e-5f

// GEMM1 tiling: 128x128 blocks, plain fp16 mma.sync (fp32 accum), 3-stage pipe
#define MPAD 20096       // 157 * 128
#define NPAD 896         // 7 * 128
#define BM 128
#define BN 128
#define BK 32
#define SAP 40           // A smem pitch (elems): 80B rows
#define SBP 136          // B smem pitch (elems): 272B rows
#define NKITER (F1 / BK) // 25
#define NSTAGE 3

// edge kernel grid
#define EGX 250                       // blocks per layer
#define NHW (EGX * 256 / 16)          // 4000 half-warps per layer
#define EITER (ENE / NHW)             // 30 (exact)

// ---------------- scratch (device globals; no allocation allowed) -------------
__device__ __half g_xl[(size_t)LNUM * NN * HC];   // fp16 (halves gather traffic)
__device__ __half g_xr[(size_t)LNUM * NN * HC];
__device__ float  g_degw[LNUM * NN * 2];     // (cnt, wsum) interleaved
__device__ float  g_denom[LNUM * NN * 2];
__device__ float  g_num[LNUM * NN * HC];
__device__ double g_bnsum[LNUM * CC];
__device__ double g_bnsq[LNUM * CC];
__device__ float  g_bnscale[F1];
__device__ float  g_bnshift[F1];
__device__ __half g_h[(size_t)NN * F1];      // concat features pre-BN (fp16)
__device__ __half g_hid[(size_t)NN * F1];    // MLP hidden (fp16)
__device__ __half g_Ah[(size_t)MPAD * F1];
__device__ __half g_Bh[(size_t)F1 * NPAD];

// ---------------- helpers -----------------------------------------------------
__device__ __forceinline__ void redAddV4(float* p, float a, float b, float c, float d) {
    asm volatile("red.global.add.v4.f32 [%0], {%1,%2,%3,%4};"
                 :: "l"(p), "f"(a), "f"(b), "f"(c), "f"(d) : "memory");
}
__device__ __forceinline__ void redAddV2(float* p, float a, float b) {
    asm volatile("red.global.add.v2.f32 [%0], {%1,%2};"
                 :: "l"(p), "f"(a), "f"(b) : "memory");
}
__device__ __forceinline__ unsigned su32(const void* p) {
    return (unsigned)__cvta_generic_to_shared(p);
}
__device__ __forceinline__ void cp16(unsigned s, const void* g) {
    asm volatile("cp.async.cg.shared.global [%0], [%1], 16;" :: "r"(s), "l"(g));
}
__device__ __forceinline__ void cp_commit() { asm volatile("cp.async.commit_group;"); }
template<int N> __device__ __forceinline__ void cp_wait() {
    asm volatile("cp.async.wait_group %0;" :: "n"(N));
}
__device__ __forceinline__ void ldsm_x4(unsigned* r, unsigned addr) {
    asm volatile("ldmatrix.sync.aligned.m8n8.x4.shared.b16 {%0,%1,%2,%3}, [%4];"
                 : "=r"(r[0]), "=r"(r[1]), "=r"(r[2]), "=r"(r[3]) : "r"(addr));
}
__device__ __forceinline__ void ldsm_x4_t(unsigned* r, unsigned addr) {
    asm volatile("ldmatrix.sync.aligned.m8n8.x4.trans.shared.b16 {%0,%1,%2,%3}, [%4];"
                 : "=r"(r[0]), "=r"(r[1]), "=r"(r[2]), "=r"(r[3]) : "r"(addr));
}
__device__ __forceinline__ void mma_f16(float* d, const unsigned* a, const unsigned* b) {
    asm volatile("mma.sync.aligned.m16n8k16.row.col.f32.f16.f16.f32 "
                 "{%0,%1,%2,%3}, {%4,%5,%6,%7}, {%8,%9}, {%0,%1,%2,%3};"
                 : "+f"(d[0]), "+f"(d[1]), "+f"(d[2]), "+f"(d[3])
                 : "r"(a[0]), "r"(a[1]), "r"(a[2]), "r"(a[3]), "r"(b[0]), "r"(b[1]));
}

// ---------------- kernels ------------------------------------------------------

__global__ void k_init() {
    long i0 = (long)blockIdx.x * blockDim.x + threadIdx.x;
    long st = (long)gridDim.x * blockDim.x;
    float4 z4 = make_float4(0.f, 0.f, 0.f, 0.f);
    float4* num4 = (float4*)g_num;
    for (long t = i0; t < (long)LNUM * NN * HC / 4; t += st) num4[t] = z4;
    float4* den4 = (float4*)g_denom;
    float4* dg4  = (float4*)g_degw;
    for (long t = i0; t < (long)LNUM * NN * 2 / 4; t += st) { den4[t] = z4; dg4[t] = z4; }
    for (long t = i0; t < (long)LNUM * CC; t += st) { g_bnsum[t] = 0.0; g_bnsq[t] = 0.0; }
}

// xl = x@Wl + bl ; xr = x@Wr + br.  One thread per (l, n, 4 features); fp16 out.
__global__ void k_xlxr(const float* __restrict__ x,
                       const float* __restrict__ Wl, const float* __restrict__ bl,
                       const float* __restrict__ Wr, const float* __restrict__ br) {
    long idx = (long)blockIdx.x * blockDim.x + threadIdx.x;
    if (idx >= (long)LNUM * NN * (HC / 4)) return;
    int j = (int)(idx % (HC / 4)) * 4;
    long r = idx / (HC / 4);
    int n = (int)(r % NN);
    int l = (int)(r / NN);
    const float* xv = x + (long)n * 5;
    float4 accl = *(const float4*)&bl[l * HC + j];
    float4 accr = *(const float4*)&br[l * HC + j];
#pragma unroll
    for (int k = 0; k < 5; k++) {
        float xk = xv[k];
        float4 wl4 = *(const float4*)&Wl[((long)l * 5 + k) * HC + j];
        float4 wr4 = *(const float4*)&Wr[((long)l * 5 + k) * HC + j];
        accl.x += xk * wl4.x; accl.y += xk * wl4.y;
        accl.z += xk * wl4.z; accl.w += xk * wl4.w;
        accr.x += xk * wr4.x; accr.y += xk * wr4.y;
        accr.z += xk * wr4.z; accr.w += xk * wr4.w;
    }
    size_t o = ((size_t)l * NN + n) * HC + j;
    __half2* dl = (__half2*)&g_xl[o];
    dl[0] = __floats2half2_rn(accl.x, accl.y);
    dl[1] = __floats2half2_rn(accl.z, accl.w);
    __half2* dr = (__half2*)&g_xr[o];
    dr[0] = __floats2half2_rn(accr.x, accr.y);
    dr[1] = __floats2half2_rn(accr.z, accr.w);
}

// in-degree + wsum; 2 edges per thread (vectorized index/weight loads)
__global__ void k_deg(const int* __restrict__ ei, const float* __restrict__ ew) {
    long idx = (long)blockIdx.x * blockDim.x + threadIdx.x;
    if (idx >= (long)LNUM * (EE / 2)) return;
    int e2 = (int)(idx % (EE / 2)) * 2;
    int l = (int)(idx / (EE / 2));
    int2   d2 = *(const int2*)&ei[((long)l * 2 + 1) * EE + e2];
    float2 w2 = *(const float2*)&ew[(long)l * EE + e2];
    float* degwL = g_degw + (long)l * NN * 2;
    redAddV2(&degwL[(long)d2.x * 2], 1.0f, w2.x);
    redAddV2(&degwL[(long)d2.y * 2], 1.0f, w2.y);
}

// FUSED edge pass.  2D grid: blockIdx.y = layer.  Each half-warp handles
// EITER=30 edges with stride NHW (exact => uniform control flow; iters 25-29
// are uniformly self loops with attr = wsum/max(cnt,1) from g_degw).
// xl/xr gathers are fp16 (uint2 per lane), converted to fp32 in registers.
__global__ void __launch_bounds__(256) k_edge(const int* __restrict__ ei,
                                              const float* __restrict__ ew,
                                              const float* __restrict__ We,
                                              const float* __restrict__ att) {
    const int l = blockIdx.y;
    const int lane = threadIdx.x & 31;
    const int sub = lane & 15;
    const int j = sub * 4;
    const int hw0 = (blockIdx.x * 256 + threadIdx.x) >> 4;

    const float4 we4 = *(const float4*)&We[l * HC + j];
    const float4 at4 = *(const float4*)&att[l * HC + j];
    const int*   srcp = ei + (long)l * 2 * EE;
    const int*   dstp = srcp + EE;
    const float* ewp  = ew + (long)l * EE;
    const __half* xlL = g_xl + (size_t)l * NN * HC;
    const __half* xrL = g_xr + (size_t)l * NN * HC;
    const float* degwL = g_degw + (long)l * NN * 2;
    float* denomL = g_denom + (long)l * NN * 2;
    float* numL   = g_num + (long)l * NN * HC;

#pragma unroll 2
    for (int it = 0; it < EITER; it++) {
        int e = hw0 + it * NHW;
        int s, d; float w;
        if (e < EE) {
            s = __ldg(srcp + e);
            d = __ldg(dstp + e);
            w = __ldg(ewp + e);
        } else {
            s = e - EE; d = s;
            float2 dw = *(const float2*)&degwL[(long)s * 2];
            w = dw.y / fmaxf(dw.x, 1.0f);
        }
        uint2 uxl = *(const uint2*)&xlL[(size_t)s * HC + j];
        uint2 uxr = *(const uint2*)&xrL[(size_t)d * HC + j];
        float2 l01 = __half22float2(*(const __half2*)&uxl.x);
        float2 l23 = __half22float2(*(const __half2*)&uxl.y);
        float2 r01 = __half22float2(*(const __half2*)&uxr.x);
        float2 r23 = __half22float2(*(const __half2*)&uxr.y);
        float t0 = l01.x + r01.x + w * we4.x;
        float t1 = l01.y + r01.y + w * we4.y;
        float t2 = l23.x + r23.x + w * we4.z;
        float t3 = l23.y + r23.y + w * we4.w;
        t0 = t0 > 0.f ? t0 : 0.2f * t0;
        t1 = t1 > 0.f ? t1 : 0.2f * t1;
        t2 = t2 > 0.f ? t2 : 0.2f * t2;
        t3 = t3 > 0.f ? t3 : 0.2f * t3;
        float v = t0 * at4.x + t1 * at4.y + t2 * at4.z + t3 * at4.w;
        v += __shfl_xor_sync(0xffffffffu, v, 1);
        v += __shfl_xor_sync(0xffffffffu, v, 2);
        v += __shfl_xor_sync(0xffffffffu, v, 4);
        float vother = __shfl_sync(0xffffffffu, v, (lane & 16) | 8);
        float p  = __expf(v);
        float p1 = __expf(vother);
        if (sub == 0) {
            redAddV2(&denomL[(long)d * 2], p, p1);
        }
        redAddV4(&numL[(long)d * HC + j],
                 l01.x * p, l01.y * p, l23.x * p, l23.y * p);
    }
}

// Node pass: normalize, head-mean, conv bias, concat write (fp16), BN partials.
__global__ void k_node(const float* __restrict__ conv_bias) {
    int l = blockIdx.x;
    int c = threadIdx.x;
    int ty = threadIdx.y;
    int base = blockIdx.y * 2000;
    float cb = conv_bias[l * CC + c];
    float s1 = 0.f, s2 = 0.f;
    for (int n = base + ty; n < base + 2000; n += 8) {
        float2 den = *(const float2*)&g_denom[((long)l * NN + n) * 2];
        float deg  = g_degw[((long)l * NN + n) * 2] + 1.0f;
        long nb = ((long)l * NN + n) * HC;
        float o = 0.5f * (g_num[nb + c] / den.x + g_num[nb + 32 + c] / den.y) / deg + cb;
        g_h[(size_t)n * F1 + l * CC + c] = __float2half_rn(o);
        s1 += o;
        s2 += o * o;
    }
    __shared__ float sm1[8][32];
    __shared__ float sm2[8][32];
    sm1[ty][c] = s1; sm2[ty][c] = s2;
    __syncthreads();
    if (ty == 0) {
        float t1 = 0.f, t2 = 0.f;
#pragma unroll
        for (int y = 0; y < 8; y++) { t1 += sm1[y][c]; t2 += sm2[y][c]; }
        atomicAdd(&g_bnsum[l * CC + c], (double)t1);
        atomicAdd(&g_bnsq[l * CC + c], (double)t2);
    }
}

// Tiny: turn BN sums into per-feature scale/shift
__global__ void k_bnstat(const float* __restrict__ gamma1, const float* __restrict__ beta1) {
    int f = blockIdx.x * blockDim.x + threadIdx.x;
    if (f >= F1) return;
    double mean = g_bnsum[f] * (1.0 / NN);
    double var  = g_bnsq[f] * (1.0 / NN) - mean * mean;
    float inv = rsqrtf((float)var + BNEPS);
    float sc = gamma1[f] * inv;
    g_bnscale[f] = sc;
    g_bnshift[f] = beta1[f] - sc * (float)mean;
}

// BN finalize + leaky(0.01) -> fp16 GEMM A operand.  4 features per thread.
__global__ void k_bnfin() {
    long idx = (long)blockIdx.x * blockDim.x + threadIdx.x;
    if (idx >= (long)MPAD * (F1 / 4)) return;
    int f = (int)(idx % (F1 / 4)) * 4;
    long row = idx / (F1 / 4);
    __half2 h0, h1;
    if (row < NN) {
        uint2 u = *(const uint2*)&g_h[row * F1 + f];
        float2 f01 = __half22float2(*(const __half2*)&u.x);
        float2 f23 = __half22float2(*(const __half2*)&u.y);
        float4 sc = *(const float4*)&g_bnscale[f];
        float4 sh = *(const float4*)&g_bnshift[f];
        float o0 = sc.x * f01.x + sh.x;
        float o1 = sc.y * f01.y + sh.y;
        float o2 = sc.z * f23.x + sh.z;
        float o3 = sc.w * f23.y + sh.w;
        o0 = o0 > 0.f ? o0 : 0.01f * o0;
        o1 = o1 > 0.f ? o1 : 0.01f * o1;
        o2 = o2 > 0.f ? o2 : 0.01f * o2;
        o3 = o3 > 0.f ? o3 : 0.01f * o3;
        h0 = __floats2half2_rn(o0, o1);
        h1 = __floats2half2_rn(o2, o3);
    } else {
        h0 = __floats2half2_rn(0.f, 0.f);
        h1 = h0;
    }
    __half2* dst = (__half2*)&g_Ah[row * F1 + f];
    dst[0] = h0;
    dst[1] = h1;
}

// W1 -> fp16 (round-to-nearest), N padded to 896
__global__ void k_cvtW1(const float* __restrict__ W1) {
    long idx = (long)blockIdx.x * blockDim.x + threadIdx.x;
    if (idx >= (long)F1 * NPAD) return;
    int n = (int)(idx % NPAD);
    int k = (int)(idx / NPAD);
    float v = (n < F1) ? W1[(long)k * F1 + n] : 0.f;
    g_Bh[idx] = __float2half_rn(v);
}

// GEMM1: g_hid = relu(A[20000,800] @ W1[800,800] + b1), plain fp16 mma.sync,
// fp32 accum, fp16 output.  128x128 tile, 8 warps of 32x64, 3-stage pipeline.
__global__ void __launch_bounds__(256, 2) k_gemm1(const float* __restrict__ bias) {
    extern __shared__ __half sm[];
    const int tid = threadIdx.x;
    const int wid = tid >> 5, lane = tid & 31;
    const int wm = wid >> 1, wn = wid & 1;      // 4 x 2 warp grid, 32x64 per warp
    const int rowBase = blockIdx.y * BM, nBase = blockIdx.x * BN;

    const int AOFF = BM * SAP;                  // 5120 elems
    const int BOFF = BK * SBP;                  // 4352 elems
    const int STAGE_E = AOFF + BOFF;            // 9472 elems (18.5 KB)

    float acc[2][8][4];
#pragma unroll
    for (int i = 0; i < 2; i++)
#pragma unroll
        for (int j = 0; j < 8; j++)
#pragma unroll
            for (int k = 0; k < 4; k++) acc[i][j][k] = 0.f;

    auto load_stage = [&](int ks, int buf) {
        const int k0 = ks * BK;
        __half* base = sm + buf * STAGE_E;
#pragma unroll
        for (int i = 0; i < 2; i++) {
            int c = tid + i * 256;
            int row = c >> 2, seg = c & 3;
            cp16(su32(base + row * SAP + seg * 8),
                 g_Ah + (size_t)(rowBase + row) * F1 + k0 + seg * 8);
        }
#pragma unroll
        for (int i = 0; i < 2; i++) {
            int c = tid + i * 256;
            int kr = c >> 4, seg = c & 15;
            cp16(su32(base + AOFF + kr * SBP + seg * 8),
                 g_Bh + (size_t)(k0 + kr) * NPAD + nBase + seg * 8);
        }
        cp_commit();
    };

    const int grp = lane >> 3, lr = lane & 7;

    auto compute_stage = [&](int buf) {
        __half* base = sm + buf * STAGE_E;
#pragma unroll
        for (int kk = 0; kk < 2; kk++) {
            unsigned af[2][4], bf[4][4];
            int acol = kk * 16 + (grp >> 1) * 8;
#pragma unroll
            for (int mt = 0; mt < 2; mt++) {
                int arow = wm * 32 + mt * 16 + (grp & 1) * 8 + lr;
                ldsm_x4(af[mt], su32(base + arow * SAP + acol));
            }
            int krow = kk * 16 + (grp & 1) * 8 + lr;
#pragma unroll
            for (int np = 0; np < 4; np++) {
                int ncol = wn * 64 + np * 16 + (grp >> 1) * 8;
                ldsm_x4_t(bf[np], su32(base + AOFF + krow * SBP + ncol));
            }
#pragma unroll
            for (int mt = 0; mt < 2; mt++)
#pragma unroll
                for (int nt = 0; nt < 8; nt++) {
                    const unsigned* b = &bf[nt >> 1][(nt & 1) * 2];
                    mma_f16(acc[mt][nt], af[mt], b);
                }
        }
    };

    load_stage(0, 0);
    load_stage(1, 1);
    for (int ks = 0; ks < NKITER; ks++) {
        if (ks + 2 < NKITER) {
            load_stage(ks + 2, (ks + 2) % NSTAGE);
            cp_wait<2>();
        } else if (ks + 1 < NKITER) {
            cp_wait<1>();
        } else {
            cp_wait<0>();
        }
        __syncthreads();
        compute_stage(ks % NSTAGE);
        __syncthreads();
    }

#pragma unroll
    for (int mt = 0; mt < 2; mt++) {
#pragma unroll
        for (int nt = 0; nt < 8; nt++) {
            int row0 = rowBase + wm * 32 + mt * 16 + (lane >> 2);
            int col0 = nBase + wn * 64 + nt * 8 + (lane & 3) * 2;
            float* a = acc[mt][nt];
            if (col0 < F1) {    // col0 even, F1 even => col0+1 < F1 too
                float b0 = bias[col0], b1 = bias[col0 + 1];
                if (row0 < NN) {
                    float v0 = fmaxf(a[0] + b0, 0.f);
                    float v1 = fmaxf(a[1] + b1, 0.f);
                    *(__half2*)&g_hid[(size_t)row0 * F1 + col0] = __floats2half2_rn(v0, v1);
                }
                if (row0 + 8 < NN) {
                    float v2 = fmaxf(a[2] + b0, 0.f);
                    float v3 = fmaxf(a[3] + b1, 0.f);
                    *(__half2*)&g_hid[(size_t)(row0 + 8) * F1 + col0] = __floats2half2_rn(v2, v3);
                }
            }
        }
    }
}

// out = g_hid[20000,800](fp16) @ W2[800,5] + b2. One warp per row.
__global__ void k_gemm2(const float* __restrict__ W2, const float* __restrict__ b2,
                        float* __restrict__ out) {
    long w = ((long)blockIdx.x * blockDim.x + threadIdx.x) >> 5;
    int lane = threadIdx.x & 31;
    if (w >= NN) return;
    const __half* hr = g_hid + (size_t)w * F1;
    float a0 = 0.f, a1 = 0.f, a2 = 0.f, a3 = 0.f, a4 = 0.f;
    for (int k4 = lane * 4; k4 < F1; k4 += 128) {
        uint2 u = *(const uint2*)(hr + k4);
        float2 f01 = __half22float2(*(const __half2*)&u.x);
        float2 f23 = __half22float2(*(const __half2*)&u.y);
        float hs[4] = {f01.x, f01.y, f23.x, f23.y};
#pragma unroll
        for (int t = 0; t < 4; t++) {
            const float* wv = W2 + (k4 + t) * 5;
            float hk = hs[t];
            a0 += hk * wv[0];
            a1 += hk * wv[1];
            a2 += hk * wv[2];
            a3 += hk * wv[3];
            a4 += hk * wv[4];
        }
    }
#pragma unroll
    for (int o = 16; o; o >>= 1) {
        a0 += __shfl_xor_sync(0xffffffffu, a0, o);
        a1 += __shfl_xor_sync(0xffffffffu, a1, o);
        a2 += __shfl_xor_sync(0xffffffffu, a2, o);
        a3 += __shfl_xor_sync(0xffffffffu, a3, o);
        a4 += __shfl_xor_sync(0xffffffffu, a4, o);
    }
    if (lane == 0) {
        out[w * 5 + 0] = a0 + b2[0];
        out[w * 5 + 1] = a1 + b2[1];
        out[w * 5 + 2] = a2 + b2[2];
        out[w * 5 + 3] = a3 + b2[3];
        out[w * 5 + 4] = a4 + b2[4];
    }
}

// ---------------- launcher ----------------------------------------------------
extern "C" void kernel_launch(void* const* d_in, const int* in_sizes, int n_in,
                              void* d_out, int out_size) {
    const float* x     = (const float*)d_in[0];
    const int*   ei    = (const int*)d_in[1];
    const float* ew    = (const float*)d_in[2];
    const float* Wl    = (const float*)d_in[3];
    const float* bl    = (const float*)d_in[4];
    const float* Wr    = (const float*)d_in[5];
    const float* br    = (const float*)d_in[6];
    const float* We    = (const float*)d_in[7];
    const float* att   = (const float*)d_in[8];
    const float* cb    = (const float*)d_in[9];
    const float* gamma = (const float*)d_in[10];
    const float* beta  = (const float*)d_in[11];
    const float* W1    = (const float*)d_in[12];
    const float* b1    = (const float*)d_in[13];
    const float* W2    = (const float*)d_in[14];
    const float* b2    = (const float*)d_in[15];
    float* out = (float*)d_out;

    const int SMEM_BYTES = NSTAGE * (BM * SAP + BK * SBP) * (int)sizeof(__half);
    cudaFuncSetAttribute(k_gemm1, cudaFuncAttributeMaxDynamicSharedMemorySize, SMEM_BYTES);

    k_init<<<2048, 256>>>();                                          // 0
    {   // xl/xr (vectorized, fp16 out)                                 1
        long total = (long)LNUM * NN * (HC / 4);
        k_xlxr<<<(int)((total + 255) / 256), 256>>>(x, Wl, bl, Wr, br);
    }
    {   // degrees (2 edges / thread)                                   2
        long total = (long)LNUM * (EE / 2);
        k_deg<<<(int)((total + 255) / 256), 256>>>(ei, ew);
    }
    {   // fused edge pass (fp16 gathers)                               3 (ncu target)
        dim3 grid(EGX, LNUM);
        k_edge<<<grid, 256>>>(ei, ew, We, att);
    }
    {   // node pass (fp16 h)                                           4
        dim3 grid(LNUM, 10);
        dim3 block(32, 8);
        k_node<<<grid, block>>>(cb);
    }
    {   // W1 -> fp16                                                   5
        long total = (long)F1 * NPAD;
        k_cvtW1<<<(int)((total + 255) / 256), 256>>>(W1);
    }
    {   // BN scale/shift                                               6
        k_bnstat<<<(F1 + 255) / 256, 256>>>(gamma, beta);
    }
    {   // BN finalize -> fp16 A operand (vectorized x4)                7
        long total = (long)MPAD * (F1 / 4);
        k_bnfin<<<(int)((total + 255) / 256), 256>>>();
    }
    {   // MLP layer 1 (fp16 tensor cores, 128x128, 3-stage)            8
        dim3 grid(NPAD / BN, MPAD / BM);
        k_gemm1<<<grid, 256, SMEM_BYTES>>>(b1);
    }
    {   // MLP layer 2 (fp16 input)                                     9
        long threads = (long)NN * 32;
        k_gemm2<<<(int)((threads + 255) / 256), 256>>>(W2, b2, out);
    }
    (void)in_sizes; (void)n_in; (void)out_size;
}